// round 1
// baseline (speedup 1.0000x reference)
#include <cuda_runtime.h>

#define BB 16
#define CC 256
#define HH 96
#define WW 96
#define QKD 64
#define PP (HH*WW)          // 9216
#define JTOT 384            // 64 + 64 + 256

// ---------------- scratch (static device memory; no allocs allowed) ----------
__device__ float g_Wcat[JTOT*CC];            // concatenated [Wq; Wk; Wv], row-major [384][256]
__device__ float g_bcat[JTOT];
__device__ float g_Qt[BB*WW*HH*QKD];         // [b][w][h][q]   37.7 MB
__device__ float g_Kt[BB*WW*HH*QKD];         // [b][w][h][q]
__device__ float g_Vt[(size_t)BB*WW*HH*CC];  // [b][w][g][c]  151 MB
__device__ float g_Ot[(size_t)BB*WW*HH*CC];  // [b][w][h][c]  151 MB

// ---------------- kernel 0: concat weights -----------------------------------
__global__ void prep_kernel(const float* __restrict__ Wq, const float* __restrict__ bq,
                            const float* __restrict__ Wk, const float* __restrict__ bk,
                            const float* __restrict__ Wv, const float* __restrict__ bv) {
    int i = blockIdx.x * blockDim.x + threadIdx.x;
    if (i < JTOT*CC) {
        int j = i / CC, k = i % CC;
        float v;
        if (j < 64)       v = Wq[j*CC + k];
        else if (j < 128) v = Wk[(j-64)*CC + k];
        else              v = Wv[(j-128)*CC + k];
        g_Wcat[i] = v;
    }
    if (i < JTOT) {
        g_bcat[i] = (i < 64) ? bq[i] : (i < 128) ? bk[i-64] : bv[i-128];
    }
}

// ---------------- kernel 1: QKV projection GEMM ------------------------------
// C[j,p] = sum_k Wcat[j,k] * x[b,k,p] + bias[j],  j tile 64, p tile 64, k tile 16.
// Output written TRANSPOSED per pixel: [b][w][h][j] so kernel 2 loads are contiguous.
__global__ __launch_bounds__(256) void qkv_kernel(const float* __restrict__ x) {
    __shared__ float As[16][64];   // [k][j]
    __shared__ float Bs[16][64];   // [k][p]
    int tid = threadIdx.x;
    int bx = blockIdx.x;           // p tile (144)
    int by = blockIdx.y;           // j tile (6): 0=Q 1=K 2..5=V
    int bz = blockIdx.z;           // batch
    int jBase = by * 64;
    int pBase = bx * 64;
    int tx = tid & 15, ty = tid >> 4;
    float acc[4][4] = {};
    const float* xb = x + (size_t)bz * CC * PP;

    for (int k0 = 0; k0 < CC; k0 += 16) {
        {   // A tile: thread t -> row j=t/4, 4 consecutive k
            int j = tid >> 2, kq = (tid & 3) * 4;
            float4 a = *(const float4*)&g_Wcat[(jBase + j)*CC + k0 + kq];
            As[kq+0][j] = a.x; As[kq+1][j] = a.y; As[kq+2][j] = a.z; As[kq+3][j] = a.w;
        }
        {   // B tile: thread t -> row k=t/16, 4 consecutive p (coalesced 256B rows)
            int k = tid >> 4, pq = (tid & 15) * 4;
            *(float4*)&Bs[k][pq] = *(const float4*)&xb[(size_t)(k0 + k)*PP + pBase + pq];
        }
        __syncthreads();
        #pragma unroll
        for (int kk = 0; kk < 16; kk++) {
            float4 a4 = *(float4*)&As[kk][ty*4];
            float4 b4 = *(float4*)&Bs[kk][tx*4];
            float av[4] = {a4.x, a4.y, a4.z, a4.w};
            float bv4[4] = {b4.x, b4.y, b4.z, b4.w};
            #pragma unroll
            for (int jj = 0; jj < 4; jj++)
                #pragma unroll
                for (int ii = 0; ii < 4; ii++)
                    acc[jj][ii] += av[jj] * bv4[ii];
        }
        __syncthreads();
    }

    float bias[4];
    #pragma unroll
    for (int jj = 0; jj < 4; jj++) bias[jj] = g_bcat[jBase + ty*4 + jj];

    #pragma unroll
    for (int ii = 0; ii < 4; ii++) {
        int p = pBase + tx*4 + ii;
        int w = p % WW, h = p / WW;
        float4 v;
        v.x = acc[0][ii] + bias[0];
        v.y = acc[1][ii] + bias[1];
        v.z = acc[2][ii] + bias[2];
        v.w = acc[3][ii] + bias[3];
        int col = (bz*WW + w)*HH + h;
        if (by == 0)      *(float4*)&g_Qt[col*QKD + ty*4] = v;
        else if (by == 1) *(float4*)&g_Kt[col*QKD + ty*4] = v;
        else              *(float4*)&g_Vt[(size_t)col*CC + (by-2)*64 + ty*4] = v;
    }
}

// ---------------- kernel 2: per-(b,w) column attention -----------------------
// smem: sQT[64][97] + sKT[64][97] (transposed, pitch 97 -> conflict-free) + sS[96][96]
#define SM2_FLOATS (2*64*97 + 96*96)   // 21632 floats = 86528 bytes

__global__ __launch_bounds__(256) void attn_kernel() {
    extern __shared__ float sm[];
    float* sQT = sm;                 // [k][h] pitch 97
    float* sKT = sm + 64*97;         // [k][g] pitch 97
    float* sS  = sm + 2*64*97;       // [h][g] 96x96
    float* sV  = sm;                 // reuse Q/K region after scores: [g][c] 96x64

    int tid = threadIdx.x;
    int bw = blockIdx.x;             // b*96 + w
    const float* Qg = g_Qt + bw * HH * QKD;
    const float* Kg = g_Kt + bw * HH * QKD;

    // load Q,K transposed into smem (global coalesced; STS stride 97 -> no conflicts)
    for (int i = tid; i < HH*QKD; i += 256) {
        int h = i >> 6, q = i & 63;
        sQT[q*97 + h] = Qg[i];
        sKT[q*97 + h] = Kg[i];
    }
    __syncthreads();

    // scores: 6x6 microtile per thread (16x16 thread grid)
    {
        int h0 = (tid >> 4) * 6, g0 = (tid & 15) * 6;
        float acc[6][6] = {};
        for (int k = 0; k < 64; k++) {
            float qv[6], kv[6];
            #pragma unroll
            for (int i = 0; i < 6; i++) qv[i] = sQT[k*97 + h0 + i];
            #pragma unroll
            for (int j = 0; j < 6; j++) kv[j] = sKT[k*97 + g0 + j];
            #pragma unroll
            for (int i = 0; i < 6; i++)
                #pragma unroll
                for (int j = 0; j < 6; j++)
                    acc[i][j] += qv[i] * kv[j];
        }
        #pragma unroll
        for (int i = 0; i < 6; i++)
            #pragma unroll
            for (int j = 0; j < 6; j++)
                sS[(h0+i)*96 + g0 + j] = acc[i][j];
    }
    __syncthreads();

    // softmax over g: warp per row group (8 warps x 12 rows), 96 = 3 lanes-strides
    {
        int warp = tid >> 5, lane = tid & 31;
        for (int r = 0; r < 12; r++) {
            int h = warp*12 + r;
            float v0 = sS[h*96 + lane];
            float v1 = sS[h*96 + 32 + lane];
            float v2 = sS[h*96 + 64 + lane];
            float m = fmaxf(v0, fmaxf(v1, v2));
            #pragma unroll
            for (int o = 16; o > 0; o >>= 1) m = fmaxf(m, __shfl_xor_sync(0xffffffffu, m, o));
            float e0 = __expf(v0 - m), e1 = __expf(v1 - m), e2 = __expf(v2 - m);
            float s = e0 + e1 + e2;
            #pragma unroll
            for (int o = 16; o > 0; o >>= 1) s += __shfl_xor_sync(0xffffffffu, s, o);
            float inv = 1.0f / s;
            sS[h*96 + lane]      = e0 * inv;
            sS[h*96 + 32 + lane] = e1 * inv;
            sS[h*96 + 64 + lane] = e2 * inv;
        }
    }
    __syncthreads();

    // AV: out[h][c] = sum_g attn[h][g] * V[g][c]; V streamed in 64-channel chunks
    const float* Vg = g_Vt + (size_t)bw * HH * CC;
    float*       Og = g_Ot + (size_t)bw * HH * CC;
    int h0 = (tid >> 4) * 6;
    int cc = (tid & 15) * 4;
    for (int c0 = 0; c0 < CC; c0 += 64) {
        for (int i = tid; i < HH*64/4; i += 256) {
            int g = i >> 4, cq = (i & 15) * 4;
            *(float4*)&sV[g*64 + cq] = *(const float4*)&Vg[(size_t)g*CC + c0 + cq];
        }
        __syncthreads();
        float acc[6][4] = {};
        for (int g = 0; g < 96; g++) {
            float4 v4 = *(float4*)&sV[g*64 + cc];
            #pragma unroll
            for (int i = 0; i < 6; i++) {
                float s = sS[(h0+i)*96 + g];
                acc[i][0] += s * v4.x;
                acc[i][1] += s * v4.y;
                acc[i][2] += s * v4.z;
                acc[i][3] += s * v4.w;
            }
        }
        #pragma unroll
        for (int i = 0; i < 6; i++) {
            float4 o;
            o.x = acc[i][0]; o.y = acc[i][1]; o.z = acc[i][2]; o.w = acc[i][3];
            *(float4*)&Og[(size_t)(h0+i)*CC + c0 + cc] = o;
        }
        __syncthreads();
    }
}

// ---------------- kernel 3: transpose back + residual ------------------------
// out[b][c][h][w] = gamma * Ot[b][w][h][c] + x[b][c][h][w]
__global__ __launch_bounds__(256) void out_kernel(const float* __restrict__ x,
                                                  const float* __restrict__ gamma,
                                                  float* __restrict__ out) {
    __shared__ float tile[32][33];
    int c0 = blockIdx.x * 32;
    int w0 = blockIdx.y * 32;
    int bh = blockIdx.z;
    int b = bh / HH, h = bh % HH;
    int tx = threadIdx.x, ty = threadIdx.y;   // 32 x 8
    float gm = gamma[0];
    const float* Ob = g_Ot + (size_t)b * WW * HH * CC;
    #pragma unroll
    for (int i = 0; i < 4; i++) {
        int wl = ty + i*8;
        tile[wl][tx] = Ob[(size_t)((w0 + wl)*HH + h)*CC + c0 + tx];
    }
    __syncthreads();
    size_t base = (size_t)b * CC * PP + (size_t)h * WW;
    #pragma unroll
    for (int i = 0; i < 4; i++) {
        int cl = ty + i*8;
        size_t idx = base + (size_t)(c0 + cl) * PP + w0 + tx;
        out[idx] = gm * tile[tx][cl] + x[idx];
    }
}

// ---------------- launcher ---------------------------------------------------
extern "C" void kernel_launch(void* const* d_in, const int* in_sizes, int n_in,
                              void* d_out, int out_size) {
    const float* x     = (const float*)d_in[0];
    const float* Wq    = (const float*)d_in[1];
    const float* bq    = (const float*)d_in[2];
    const float* Wk    = (const float*)d_in[3];
    const float* bk    = (const float*)d_in[4];
    const float* Wv    = (const float*)d_in[5];
    const float* bv    = (const float*)d_in[6];
    const float* gamma = (const float*)d_in[7];
    float* out = (float*)d_out;

    cudaFuncSetAttribute(attn_kernel, cudaFuncAttributeMaxDynamicSharedMemorySize,
                         SM2_FLOATS * (int)sizeof(float));

    prep_kernel<<<(JTOT*CC + 255)/256, 256>>>(Wq, bq, Wk, bk, Wv, bv);
    qkv_kernel<<<dim3(PP/64, JTOT/64, BB), 256>>>(x);
    attn_kernel<<<dim3(BB*WW), 256, SM2_FLOATS * sizeof(float)>>>();
    out_kernel<<<dim3(CC/32, WW/32, BB*HH), dim3(32, 8)>>>(x, gamma, out);
}

// round 3
// speedup vs baseline: 1.4093x; 1.4093x over previous
#include <cuda_runtime.h>
#include <cuda_bf16.h>
#include <cstdint>

#define BB 16
#define CC 256
#define HH 96
#define WW 96
#define QKD 64
#define PP (HH*WW)          // 9216
#define JTOT 384            // 64 + 64 + 256

// ---------------- scratch (static device memory; no allocs allowed) ----------
__device__ float g_Wcat[JTOT*CC];
__device__ float g_bcat[JTOT];
__device__ __nv_bfloat16 g_Whi[JTOT*CC];     // bf16 hi part of W
__device__ __nv_bfloat16 g_Wlo[JTOT*CC];     // bf16 lo part of W
__device__ float g_Qt[BB*WW*HH*QKD];         // [b][w][h][q]
__device__ float g_Kt[BB*WW*HH*QKD];         // [b][w][h][q]
__device__ float g_Vt[(size_t)BB*WW*HH*CC];  // [b][w][g][c]
__device__ float g_Ot[(size_t)BB*WW*HH*CC];  // [b][w][h][c]

// ---------------- warp-MMA helpers (baseline PTX, works on sm_103 target) ----
__device__ __forceinline__ uint32_t smem_u32(const void* p) {
    uint32_t a;
    asm("{ .reg .u64 t; cvta.to.shared.u64 t, %1; cvt.u32.u64 %0, t; }" : "=r"(a) : "l"(p));
    return a;
}
__device__ __forceinline__ void ldsm_x4(uint32_t* r, uint32_t addr) {
    asm volatile("ldmatrix.sync.aligned.m8n8.x4.shared.b16 {%0,%1,%2,%3}, [%4];"
        : "=r"(r[0]), "=r"(r[1]), "=r"(r[2]), "=r"(r[3]) : "r"(addr));
}
__device__ __forceinline__ void ldsm_x2t(uint32_t* r, uint32_t addr) {
    asm volatile("ldmatrix.sync.aligned.m8n8.x2.trans.shared.b16 {%0,%1}, [%2];"
        : "=r"(r[0]), "=r"(r[1]) : "r"(addr));
}
__device__ __forceinline__ void mma16816(float* d, const uint32_t* a, const uint32_t* b) {
    asm volatile("mma.sync.aligned.m16n8k16.row.col.f32.bf16.bf16.f32 "
        "{%0,%1,%2,%3}, {%4,%5,%6,%7}, {%8,%9}, {%0,%1,%2,%3};"
        : "+f"(d[0]), "+f"(d[1]), "+f"(d[2]), "+f"(d[3])
        : "r"(a[0]), "r"(a[1]), "r"(a[2]), "r"(a[3]), "r"(b[0]), "r"(b[1]));
}

// ---------------- kernel 0: concat weights + bf16 hi/lo split ----------------
__global__ void prep_kernel(const float* __restrict__ Wq, const float* __restrict__ bq,
                            const float* __restrict__ Wk, const float* __restrict__ bk,
                            const float* __restrict__ Wv, const float* __restrict__ bv) {
    int i = blockIdx.x * blockDim.x + threadIdx.x;
    if (i < JTOT*CC) {
        int j = i / CC, k = i % CC;
        float v;
        if (j < 64)       v = Wq[j*CC + k];
        else if (j < 128) v = Wk[(j-64)*CC + k];
        else              v = Wv[(j-128)*CC + k];
        g_Wcat[i] = v;
        __nv_bfloat16 h = __float2bfloat16(v);
        g_Whi[i] = h;
        g_Wlo[i] = __float2bfloat16(v - __bfloat162float(h));
    }
    if (i < JTOT) {
        g_bcat[i] = (i < 64) ? bq[i] : (i < 128) ? bk[i-64] : bv[i-128];
    }
}

// ---------------- kernel 1: QKV projection via bf16x3 warp MMA ---------------
// C[j,p] = sum_k W[j,k]*x[b,k,p] + bias[j]; block tile 128j x 128p, K chunks 64.
// A (W): smem [128 j][72 pitch bf16], k-contiguous -> ldmatrix.x4 (row-major A)
// B (x): smem [64 k][136 pitch bf16], p-contiguous -> ldmatrix.x2.trans (col-major B)
#define A_PITCH_B 144           // 72 bf16
#define B_PITCH_B 272           // 136 bf16
#define OFF_AHI   0
#define OFF_ALO   18432
#define OFF_BHI   36864
#define OFF_BLO   54272
#define OFF_BIAS  71680
#define OFF_STAGE 0             // epilogue reuses staging region
#define STG_PITCH 130           // floats
#define QKV_SMEM  72192

__global__ __launch_bounds__(256) void qkv_mma_kernel(const float* __restrict__ x) {
    extern __shared__ __align__(1024) char smq[];
    uint32_t sb = smem_u32(smq);
    int tid = threadIdx.x;
    int wid = tid >> 5, lane = tid & 31;
    int jBase = blockIdx.y * 128;     // 3 tiles: 0 = Q|K, 1 = V[0:128), 2 = V[128:256)
    int pBase = blockIdx.x * 128;     // 72 tiles
    int bz = blockIdx.z;
    const float* xb = x + (size_t)bz * CC * PP;

    int warpM = wid & 1, warpN = wid >> 1;
    uint32_t jW = warpM * 64, pW = warpN * 32;
    uint32_t aOff = (jW + (lane & 15)) * A_PITCH_B + (lane >> 4) * 16;
    uint32_t bOff = (lane & 15) * B_PITCH_B + pW * 2;

    if (tid < 128) *(float*)(smq + OFF_BIAS + tid*4) = g_bcat[jBase + tid];

    float acc[4][4][4] = {};

    for (int ch = 0; ch < 4; ch++) {
        int k0 = ch * 64;
        // ---- stage A: copy 128x64 bf16 hi/lo (uint4 = 8 bf16 per thread)
        for (int u = tid; u < 1024; u += 256) {
            int j = u >> 3, c = (u & 7) * 8;         // 8 bf16 chunks
            int gidx = (jBase + j)*CC + k0 + c;
            uint32_t so = (uint32_t)(j*A_PITCH_B + c*2);
            *(uint4*)(smq + OFF_AHI + so) = *(const uint4*)&g_Whi[gidx];
            *(uint4*)(smq + OFF_ALO + so) = *(const uint4*)&g_Wlo[gidx];
        }
        // ---- stage B: x[k][p] natural layout, convert fp32->bf16 hi/lo
        for (int u = tid; u < 2048; u += 256) {
            int k = u >> 5, p4 = (u & 31) * 4;
            float4 v = *(const float4*)&xb[(size_t)(k0 + k)*PP + pBase + p4];
            __nv_bfloat162 h0 = __float22bfloat162_rn(make_float2(v.x, v.y));
            __nv_bfloat162 h1 = __float22bfloat162_rn(make_float2(v.z, v.w));
            float2 f0 = __bfloat1622float2(h0);
            float2 f1 = __bfloat1622float2(h1);
            __nv_bfloat162 l0 = __float22bfloat162_rn(make_float2(v.x - f0.x, v.y - f0.y));
            __nv_bfloat162 l1 = __float22bfloat162_rn(make_float2(v.z - f1.x, v.w - f1.y));
            uint32_t so = (uint32_t)(k*B_PITCH_B + p4*2);
            *(uint2*)(smq + OFF_BHI + so) = make_uint2(
                *(uint32_t*)&h0, *(uint32_t*)&h1);
            *(uint2*)(smq + OFF_BLO + so) = make_uint2(
                *(uint32_t*)&l0, *(uint32_t*)&l1);
        }
        __syncthreads();

        // ---- 3 passes: (Ahi,Bhi), (Ahi,Blo), (Alo,Bhi)
        #pragma unroll
        for (int pass = 0; pass < 3; pass++) {
            uint32_t aB = sb + ((pass == 2) ? OFF_ALO : OFF_AHI) + aOff;
            uint32_t bB = sb + ((pass == 1) ? OFF_BLO : OFF_BHI) + bOff;
            #pragma unroll
            for (int ks = 0; ks < 4; ks++) {
                uint32_t af[4][4], bf[4][2];
                #pragma unroll
                for (int mi = 0; mi < 4; mi++)
                    ldsm_x4(af[mi], aB + mi*(16*A_PITCH_B) + ks*32);
                #pragma unroll
                for (int ni = 0; ni < 4; ni++)
                    ldsm_x2t(bf[ni], bB + ks*(16*B_PITCH_B) + ni*16);
                #pragma unroll
                for (int mi = 0; mi < 4; mi++)
                    #pragma unroll
                    for (int ni = 0; ni < 4; ni++)
                        mma16816(acc[mi][ni], af[mi], bf[ni]);
            }
        }
        __syncthreads();
    }

    // ---- epilogue: acc frags -> stage[j][p] (pitch 130) -> routed stores
    float* stg = (float*)(smq + OFF_STAGE);
    {
        int r = lane >> 2, c2 = (lane & 3) * 2;
        #pragma unroll
        for (int mi = 0; mi < 4; mi++)
            #pragma unroll
            for (int ni = 0; ni < 4; ni++) {
                int j = jW + mi*16 + r;
                int p = pW + ni*8 + c2;
                *(float2*)&stg[j*STG_PITCH + p]       = make_float2(acc[mi][ni][0], acc[mi][ni][1]);
                *(float2*)&stg[(j + 8)*STG_PITCH + p] = make_float2(acc[mi][ni][2], acc[mi][ni][3]);
            }
    }
    __syncthreads();

    int by = blockIdx.y;
    const float* sBias = (const float*)(smq + OFF_BIAS);
    for (int idx = tid; idx < 128*128; idx += 256) {
        int pl = idx >> 7, j = idx & 127;
        float val = stg[j*STG_PITCH + pl] + sBias[j];
        int p = pBase + pl;
        int h = p / WW, w = p - h*WW;
        int col = (bz*WW + w)*HH + h;
        if (by == 0) {
            if (j < 64) g_Qt[col*QKD + j]        = val;
            else        g_Kt[col*QKD + (j - 64)] = val;
        } else {
            g_Vt[(size_t)col*CC + (by - 1)*128 + j] = val;
        }
    }
}

// ---------------- kernel 2: per-(b,w) column attention (fp32 scalar) ---------
#define SM2_FLOATS (2*64*97 + 96*96)   // 86528 bytes

__global__ __launch_bounds__(256) void attn_kernel() {
    extern __shared__ float sm[];
    float* sQT = sm;                 // [k][h] pitch 97
    float* sKT = sm + 64*97;         // [k][g] pitch 97
    float* sS  = sm + 2*64*97;       // [h][g] 96x96
    float* sV  = sm;                 // reuse Q/K region after scores

    int tid = threadIdx.x;
    int bw = blockIdx.x;
    const float* Qg = g_Qt + bw * HH * QKD;
    const float* Kg = g_Kt + bw * HH * QKD;

    for (int i = tid; i < HH*QKD; i += 256) {
        int h = i >> 6, q = i & 63;
        sQT[q*97 + h] = Qg[i];
        sKT[q*97 + h] = Kg[i];
    }
    __syncthreads();

    {
        int h0 = (tid >> 4) * 6, g0 = (tid & 15) * 6;
        float acc[6][6] = {};
        for (int k = 0; k < 64; k++) {
            float qv[6], kv[6];
            #pragma unroll
            for (int i = 0; i < 6; i++) qv[i] = sQT[k*97 + h0 + i];
            #pragma unroll
            for (int j = 0; j < 6; j++) kv[j] = sKT[k*97 + g0 + j];
            #pragma unroll
            for (int i = 0; i < 6; i++)
                #pragma unroll
                for (int j = 0; j < 6; j++)
                    acc[i][j] += qv[i] * kv[j];
        }
        #pragma unroll
        for (int i = 0; i < 6; i++)
            #pragma unroll
            for (int j = 0; j < 6; j++)
                sS[(h0+i)*96 + g0 + j] = acc[i][j];
    }
    __syncthreads();

    {
        int warp = tid >> 5, lane = tid & 31;
        for (int r = 0; r < 12; r++) {
            int h = warp*12 + r;
            float v0 = sS[h*96 + lane];
            float v1 = sS[h*96 + 32 + lane];
            float v2 = sS[h*96 + 64 + lane];
            float m = fmaxf(v0, fmaxf(v1, v2));
            #pragma unroll
            for (int o = 16; o > 0; o >>= 1) m = fmaxf(m, __shfl_xor_sync(0xffffffffu, m, o));
            float e0 = __expf(v0 - m), e1 = __expf(v1 - m), e2 = __expf(v2 - m);
            float ssum = e0 + e1 + e2;
            #pragma unroll
            for (int o = 16; o > 0; o >>= 1) ssum += __shfl_xor_sync(0xffffffffu, ssum, o);
            float inv = 1.0f / ssum;
            sS[h*96 + lane]      = e0 * inv;
            sS[h*96 + 32 + lane] = e1 * inv;
            sS[h*96 + 64 + lane] = e2 * inv;
        }
    }
    __syncthreads();

    const float* Vg = g_Vt + (size_t)bw * HH * CC;
    float*       Og = g_Ot + (size_t)bw * HH * CC;
    int h0 = (tid >> 4) * 6;
    int cc = (tid & 15) * 4;
    for (int c0 = 0; c0 < CC; c0 += 64) {
        for (int i = tid; i < HH*64/4; i += 256) {
            int g = i >> 4, cq = (i & 15) * 4;
            *(float4*)&sV[g*64 + cq] = *(const float4*)&Vg[(size_t)g*CC + c0 + cq];
        }
        __syncthreads();
        float acc[6][4] = {};
        for (int g = 0; g < 96; g++) {
            float4 v4 = *(float4*)&sV[g*64 + cc];
            #pragma unroll
            for (int i = 0; i < 6; i++) {
                float s = sS[(h0+i)*96 + g];
                acc[i][0] += s * v4.x;
                acc[i][1] += s * v4.y;
                acc[i][2] += s * v4.z;
                acc[i][3] += s * v4.w;
            }
        }
        #pragma unroll
        for (int i = 0; i < 6; i++) {
            float4 o;
            o.x = acc[i][0]; o.y = acc[i][1]; o.z = acc[i][2]; o.w = acc[i][3];
            *(float4*)&Og[(size_t)(h0+i)*CC + c0 + cc] = o;
        }
        __syncthreads();
    }
}

// ---------------- kernel 3: transpose back + residual ------------------------
__global__ __launch_bounds__(256) void out_kernel(const float* __restrict__ x,
                                                  const float* __restrict__ gamma,
                                                  float* __restrict__ out) {
    __shared__ float tile[32][33];
    int c0 = blockIdx.x * 32;
    int w0 = blockIdx.y * 32;
    int bh = blockIdx.z;
    int b = bh / HH, h = bh % HH;
    int tx = threadIdx.x, ty = threadIdx.y;   // 32 x 8
    float gm = gamma[0];
    const float* Ob = g_Ot + (size_t)b * WW * HH * CC;
    #pragma unroll
    for (int i = 0; i < 4; i++) {
        int wl = ty + i*8;
        tile[wl][tx] = Ob[(size_t)((w0 + wl)*HH + h)*CC + c0 + tx];
    }
    __syncthreads();
    size_t base = (size_t)b * CC * PP + (size_t)h * WW;
    #pragma unroll
    for (int i = 0; i < 4; i++) {
        int cl = ty + i*8;
        size_t idx = base + (size_t)(c0 + cl) * PP + w0 + tx;
        out[idx] = gm * tile[tx][cl] + x[idx];
    }
}

// ---------------- launcher ---------------------------------------------------
extern "C" void kernel_launch(void* const* d_in, const int* in_sizes, int n_in,
                              void* d_out, int out_size) {
    const float* x     = (const float*)d_in[0];
    const float* Wq    = (const float*)d_in[1];
    const float* bq    = (const float*)d_in[2];
    const float* Wk    = (const float*)d_in[3];
    const float* bk    = (const float*)d_in[4];
    const float* Wv    = (const float*)d_in[5];
    const float* bv    = (const float*)d_in[6];
    const float* gamma = (const float*)d_in[7];
    float* out = (float*)d_out;

    cudaFuncSetAttribute(qkv_mma_kernel, cudaFuncAttributeMaxDynamicSharedMemorySize, QKV_SMEM);
    cudaFuncSetAttribute(attn_kernel, cudaFuncAttributeMaxDynamicSharedMemorySize,
                         SM2_FLOATS * (int)sizeof(float));

    prep_kernel<<<(JTOT*CC + 255)/256, 256>>>(Wq, bq, Wk, bk, Wv, bv);
    qkv_mma_kernel<<<dim3(PP/128, 3, BB), 256, QKV_SMEM>>>(x);
    attn_kernel<<<dim3(BB*WW), 256, SM2_FLOATS * sizeof(float)>>>();
    out_kernel<<<dim3(CC/32, WW/32, BB*HH), dim3(32, 8)>>>(x, gamma, out);
}

// round 4
// speedup vs baseline: 1.5921x; 1.1297x over previous
#include <cuda_runtime.h>
#include <cuda_bf16.h>
#include <cstdint>

#define BB 16
#define CC 256
#define HH 96
#define WW 96
#define QKD 64
#define PP (HH*WW)          // 9216
#define JTOT 384            // 64 + 64 + 256

// ---------------- scratch (static device memory; no allocs allowed) ----------
__device__ float g_Wcat[JTOT*CC];
__device__ float g_bcat[JTOT];
__device__ __nv_bfloat16 g_Whi[JTOT*CC];
__device__ __nv_bfloat16 g_Wlo[JTOT*CC];
__device__ float g_Qt[BB*WW*HH*QKD];         // [b][w][h][q]
__device__ float g_Kt[BB*WW*HH*QKD];         // [b][w][h][q]
__device__ float g_Vt[(size_t)BB*WW*HH*CC];  // [b][w][g][c]
__device__ float g_Ot[(size_t)BB*WW*HH*CC];  // [b][w][h][c]

// ---------------- warp-MMA helpers (baseline PTX, sm_103-safe) ---------------
__device__ __forceinline__ uint32_t smem_u32(const void* p) {
    uint32_t a;
    asm("{ .reg .u64 t; cvta.to.shared.u64 t, %1; cvt.u32.u64 %0, t; }" : "=r"(a) : "l"(p));
    return a;
}
__device__ __forceinline__ void ldsm_x4(uint32_t* r, uint32_t addr) {
    asm volatile("ldmatrix.sync.aligned.m8n8.x4.shared.b16 {%0,%1,%2,%3}, [%4];"
        : "=r"(r[0]), "=r"(r[1]), "=r"(r[2]), "=r"(r[3]) : "r"(addr));
}
__device__ __forceinline__ void ldsm_x2(uint32_t* r, uint32_t addr) {
    asm volatile("ldmatrix.sync.aligned.m8n8.x2.shared.b16 {%0,%1}, [%2];"
        : "=r"(r[0]), "=r"(r[1]) : "r"(addr));
}
__device__ __forceinline__ void ldsm_x2t(uint32_t* r, uint32_t addr) {
    asm volatile("ldmatrix.sync.aligned.m8n8.x2.trans.shared.b16 {%0,%1}, [%2];"
        : "=r"(r[0]), "=r"(r[1]) : "r"(addr));
}
__device__ __forceinline__ void mma16816(float* d, const uint32_t* a, const uint32_t* b) {
    asm volatile("mma.sync.aligned.m16n8k16.row.col.f32.bf16.bf16.f32 "
        "{%0,%1,%2,%3}, {%4,%5,%6,%7}, {%8,%9}, {%0,%1,%2,%3};"
        : "+f"(d[0]), "+f"(d[1]), "+f"(d[2]), "+f"(d[3])
        : "r"(a[0]), "r"(a[1]), "r"(a[2]), "r"(a[3]), "r"(b[0]), "r"(b[1]));
}
__device__ __forceinline__ void cvt_hilo(float4 v, uint2& hi, uint2& lo) {
    __nv_bfloat162 h0 = __float22bfloat162_rn(make_float2(v.x, v.y));
    __nv_bfloat162 h1 = __float22bfloat162_rn(make_float2(v.z, v.w));
    float2 f0 = __bfloat1622float2(h0), f1 = __bfloat1622float2(h1);
    __nv_bfloat162 l0 = __float22bfloat162_rn(make_float2(v.x - f0.x, v.y - f0.y));
    __nv_bfloat162 l1 = __float22bfloat162_rn(make_float2(v.z - f1.x, v.w - f1.y));
    hi = make_uint2(*(uint32_t*)&h0, *(uint32_t*)&h1);
    lo = make_uint2(*(uint32_t*)&l0, *(uint32_t*)&l1);
}

// ---------------- kernel 0: concat weights + bf16 hi/lo split ----------------
__global__ void prep_kernel(const float* __restrict__ Wq, const float* __restrict__ bq,
                            const float* __restrict__ Wk, const float* __restrict__ bk,
                            const float* __restrict__ Wv, const float* __restrict__ bv) {
    int i = blockIdx.x * blockDim.x + threadIdx.x;
    if (i < JTOT*CC) {
        int j = i / CC, k = i % CC;
        float v;
        if (j < 64)       v = Wq[j*CC + k];
        else if (j < 128) v = Wk[(j-64)*CC + k];
        else              v = Wv[(j-128)*CC + k];
        g_Wcat[i] = v;
        __nv_bfloat16 h = __float2bfloat16(v);
        g_Whi[i] = h;
        g_Wlo[i] = __float2bfloat16(v - __bfloat162float(h));
    }
    if (i < JTOT) {
        g_bcat[i] = (i < 64) ? bq[i] : (i < 128) ? bk[i-64] : bv[i-128];
    }
}

// ---------------- kernel 1: QKV projection via bf16x3 warp MMA ---------------
#define A_PITCH_B 144
#define B_PITCH_B 272
#define OFF_AHI   0
#define OFF_ALO   18432
#define OFF_BHI   36864
#define OFF_BLO   54272
#define OFF_BIAS  71680
#define OFF_STAGE 0
#define STG_PITCH 130
#define QKV_SMEM  72192

__global__ __launch_bounds__(256) void qkv_mma_kernel(const float* __restrict__ x) {
    extern __shared__ __align__(1024) char smq[];
    uint32_t sb = smem_u32(smq);
    int tid = threadIdx.x;
    int wid = tid >> 5, lane = tid & 31;
    int jBase = blockIdx.y * 128;
    int pBase = blockIdx.x * 128;
    int bz = blockIdx.z;
    const float* xb = x + (size_t)bz * CC * PP;

    int warpM = wid & 1, warpN = wid >> 1;
    uint32_t jW = warpM * 64, pW = warpN * 32;
    uint32_t aOff = (jW + (lane & 15)) * A_PITCH_B + (lane >> 4) * 16;
    uint32_t bOff = (lane & 15) * B_PITCH_B + pW * 2;

    if (tid < 128) *(float*)(smq + OFF_BIAS + tid*4) = g_bcat[jBase + tid];

    float acc[4][4][4] = {};

    for (int ch = 0; ch < 4; ch++) {
        int k0 = ch * 64;
        for (int u = tid; u < 1024; u += 256) {
            int j = u >> 3, c = (u & 7) * 8;
            int gidx = (jBase + j)*CC + k0 + c;
            uint32_t so = (uint32_t)(j*A_PITCH_B + c*2);
            *(uint4*)(smq + OFF_AHI + so) = *(const uint4*)&g_Whi[gidx];
            *(uint4*)(smq + OFF_ALO + so) = *(const uint4*)&g_Wlo[gidx];
        }
        for (int u = tid; u < 2048; u += 256) {
            int k = u >> 5, p4 = (u & 31) * 4;
            float4 v = *(const float4*)&xb[(size_t)(k0 + k)*PP + pBase + p4];
            uint2 hi, lo; cvt_hilo(v, hi, lo);
            uint32_t so = (uint32_t)(k*B_PITCH_B + p4*2);
            *(uint2*)(smq + OFF_BHI + so) = hi;
            *(uint2*)(smq + OFF_BLO + so) = lo;
        }
        __syncthreads();

        #pragma unroll
        for (int pass = 0; pass < 3; pass++) {
            uint32_t aB = sb + ((pass == 2) ? OFF_ALO : OFF_AHI) + aOff;
            uint32_t bB = sb + ((pass == 1) ? OFF_BLO : OFF_BHI) + bOff;
            #pragma unroll
            for (int ks = 0; ks < 4; ks++) {
                uint32_t af[4][4], bf[4][2];
                #pragma unroll
                for (int mi = 0; mi < 4; mi++)
                    ldsm_x4(af[mi], aB + mi*(16*A_PITCH_B) + ks*32);
                #pragma unroll
                for (int ni = 0; ni < 4; ni++)
                    ldsm_x2t(bf[ni], bB + ks*(16*B_PITCH_B) + ni*16);
                #pragma unroll
                for (int mi = 0; mi < 4; mi++)
                    #pragma unroll
                    for (int ni = 0; ni < 4; ni++)
                        mma16816(acc[mi][ni], af[mi], bf[ni]);
            }
        }
        __syncthreads();
    }

    float* stg = (float*)(smq + OFF_STAGE);
    {
        int r = lane >> 2, c2 = (lane & 3) * 2;
        #pragma unroll
        for (int mi = 0; mi < 4; mi++)
            #pragma unroll
            for (int ni = 0; ni < 4; ni++) {
                int j = jW + mi*16 + r;
                int p = pW + ni*8 + c2;
                *(float2*)&stg[j*STG_PITCH + p]       = make_float2(acc[mi][ni][0], acc[mi][ni][1]);
                *(float2*)&stg[(j + 8)*STG_PITCH + p] = make_float2(acc[mi][ni][2], acc[mi][ni][3]);
            }
    }
    __syncthreads();

    int by = blockIdx.y;
    const float* sBias = (const float*)(smq + OFF_BIAS);
    for (int idx = tid; idx < 128*128; idx += 256) {
        int pl = idx >> 7, j = idx & 127;
        float val = stg[j*STG_PITCH + pl] + sBias[j];
        int p = pBase + pl;
        int h = p / WW, w = p - h*WW;
        int col = (bz*WW + w)*HH + h;
        if (by == 0) {
            if (j < 64) g_Qt[col*QKD + j]        = val;
            else        g_Kt[col*QKD + (j - 64)] = val;
        } else {
            g_Vt[(size_t)col*CC + (by - 1)*128 + j] = val;
        }
    }
}

// ---------------- kernel 2: per-(b,w) column attention, bf16x3 warp MMA ------
// smem layout (bytes):
//   phase1: sQh 0..13824, sQl 13824.., sKh 27648.., sKl 41472..55296; sS 55296..93696
//   phase2: sAh 0..19968, sAl 19968..39936 (overlay Q/K)
//   phase3: sVh 55296..69120, sVl 69120..82944 (overlay S); sO 55296..81408 (after V read)
#define AT_QK_PITCH 144   // bytes (72 bf16)
#define AT_S_PITCH  100   // floats
#define AT_A_PITCH  208   // bytes (104 bf16)
#define AT_V_PITCH  144   // bytes
#define AT_O_PITCH  68    // floats
#define AOFF_QH 0
#define AOFF_QL 13824
#define AOFF_KH 27648
#define AOFF_KL 41472
#define AOFF_AH 0
#define AOFF_AL 19968
#define AOFF_S  55296
#define AOFF_VH 55296
#define AOFF_VL 69120
#define AOFF_O  55296
#define ATT_SMEM 93696

__global__ __launch_bounds__(256) void attn_mma_kernel() {
    extern __shared__ __align__(128) char sma[];
    uint32_t sb = smem_u32(sma);
    int tid = threadIdx.x;
    int wid = tid >> 5, lane = tid & 31;
    int bw = blockIdx.x;
    const float* Qg = g_Qt + (size_t)bw * HH * QKD;
    const float* Kg = g_Kt + (size_t)bw * HH * QKD;

    // ---- stage Q,K as bf16 hi/lo [h][72 pitch]
    for (int i = tid; i < 1536; i += 256) {
        int h = i >> 4, k4 = (i & 15) * 4;
        uint32_t so = (uint32_t)(h*AT_QK_PITCH + k4*2);
        uint2 hi, lo;
        cvt_hilo(*(const float4*)&Qg[h*QKD + k4], hi, lo);
        *(uint2*)(sma + AOFF_QH + so) = hi;
        *(uint2*)(sma + AOFF_QL + so) = lo;
        cvt_hilo(*(const float4*)&Kg[h*QKD + k4], hi, lo);
        *(uint2*)(sma + AOFF_KH + so) = hi;
        *(uint2*)(sma + AOFF_KL + so) = lo;
    }
    __syncthreads();

    int warpM = wid & 1, warpN = wid >> 1;
    int m0 = warpM * 48;

    // ---- scores: S[h,g] = sum_k Q[h,k]K[g,k], warp tile 48m x 24n
    {
        int n0 = warpN * 24;
        float acc[3][3][4] = {};
        uint32_t aOff = (uint32_t)((m0 + (lane & 15))*AT_QK_PITCH + (lane >> 4)*16);
        uint32_t bOff = (uint32_t)((n0 + (lane & 7))*AT_QK_PITCH + ((lane >> 3) & 1)*16);
        #pragma unroll
        for (int pass = 0; pass < 3; pass++) {
            uint32_t aB = sb + ((pass == 2) ? AOFF_QL : AOFF_QH) + aOff;
            uint32_t bB = sb + ((pass == 1) ? AOFF_KL : AOFF_KH) + bOff;
            #pragma unroll
            for (int ks = 0; ks < 4; ks++) {
                uint32_t af[3][4], bf[3][2];
                #pragma unroll
                for (int mi = 0; mi < 3; mi++)
                    ldsm_x4(af[mi], aB + mi*(16*AT_QK_PITCH) + ks*32);
                #pragma unroll
                for (int nj = 0; nj < 3; nj++)
                    ldsm_x2(bf[nj], bB + nj*(8*AT_QK_PITCH) + ks*32);
                #pragma unroll
                for (int mi = 0; mi < 3; mi++)
                    #pragma unroll
                    for (int nj = 0; nj < 3; nj++)
                        mma16816(acc[mi][nj], af[mi], bf[nj]);
            }
        }
        float* sS = (float*)(sma + AOFF_S);
        int r = lane >> 2, c2 = (lane & 3) * 2;
        #pragma unroll
        for (int mi = 0; mi < 3; mi++)
            #pragma unroll
            for (int nj = 0; nj < 3; nj++) {
                int row = m0 + mi*16 + r, col = n0 + nj*8 + c2;
                *(float2*)&sS[row*AT_S_PITCH + col]     = make_float2(acc[mi][nj][0], acc[mi][nj][1]);
                *(float2*)&sS[(row+8)*AT_S_PITCH + col] = make_float2(acc[mi][nj][2], acc[mi][nj][3]);
            }
    }
    __syncthreads();

    // ---- softmax over g (warp per 12 rows) + emit A as bf16 hi/lo [h][104]
    {
        float* sS = (float*)(sma + AOFF_S);
        __nv_bfloat16* sAh = (__nv_bfloat16*)(sma + AOFF_AH);
        __nv_bfloat16* sAl = (__nv_bfloat16*)(sma + AOFF_AL);
        for (int r = 0; r < 12; r++) {
            int h = wid*12 + r;
            float v0 = sS[h*AT_S_PITCH + lane];
            float v1 = sS[h*AT_S_PITCH + 32 + lane];
            float v2 = sS[h*AT_S_PITCH + 64 + lane];
            float m = fmaxf(v0, fmaxf(v1, v2));
            #pragma unroll
            for (int o = 16; o > 0; o >>= 1) m = fmaxf(m, __shfl_xor_sync(0xffffffffu, m, o));
            float e0 = __expf(v0 - m), e1 = __expf(v1 - m), e2 = __expf(v2 - m);
            float s = e0 + e1 + e2;
            #pragma unroll
            for (int o = 16; o > 0; o >>= 1) s += __shfl_xor_sync(0xffffffffu, s, o);
            float inv = 1.0f / s;
            float a0 = e0*inv, a1 = e1*inv, a2 = e2*inv;
            __nv_bfloat16 h0 = __float2bfloat16(a0);
            __nv_bfloat16 h1 = __float2bfloat16(a1);
            __nv_bfloat16 h2 = __float2bfloat16(a2);
            sAh[h*104 + lane]      = h0;
            sAh[h*104 + 32 + lane] = h1;
            sAh[h*104 + 64 + lane] = h2;
            sAl[h*104 + lane]      = __float2bfloat16(a0 - __bfloat162float(h0));
            sAl[h*104 + 32 + lane] = __float2bfloat16(a1 - __bfloat162float(h1));
            sAl[h*104 + 64 + lane] = __float2bfloat16(a2 - __bfloat162float(h2));
        }
    }
    __syncthreads();

    // ---- AV: O[h,c] = sum_g A[h,g] V[g,c]; c chunks of 64, warp tile 48m x 16n
    const float* Vg = g_Vt + (size_t)bw * HH * CC;
    float*       Og = g_Ot + (size_t)bw * HH * CC;
    int cW = warpN * 16;
    uint32_t aOff = (uint32_t)((m0 + (lane & 15))*AT_A_PITCH + (lane >> 4)*16);
    uint32_t bOff = (uint32_t)((lane & 15)*AT_V_PITCH + cW*2);

    for (int c0 = 0; c0 < CC; c0 += 64) {
        for (int i = tid; i < 1536; i += 256) {
            int g = i >> 4, c4 = (i & 15) * 4;
            uint2 hi, lo;
            cvt_hilo(*(const float4*)&Vg[(size_t)g*CC + c0 + c4], hi, lo);
            uint32_t so = (uint32_t)(g*AT_V_PITCH + c4*2);
            *(uint2*)(sma + AOFF_VH + so) = hi;
            *(uint2*)(sma + AOFF_VL + so) = lo;
        }
        __syncthreads();

        float acc[3][2][4] = {};
        #pragma unroll
        for (int pass = 0; pass < 3; pass++) {
            uint32_t aB = sb + ((pass == 2) ? AOFF_AL : AOFF_AH) + aOff;
            uint32_t bB = sb + ((pass == 1) ? AOFF_VL : AOFF_VH) + bOff;
            #pragma unroll
            for (int ks = 0; ks < 6; ks++) {
                uint32_t af[3][4], bf[2][2];
                #pragma unroll
                for (int mi = 0; mi < 3; mi++)
                    ldsm_x4(af[mi], aB + mi*(16*AT_A_PITCH) + ks*32);
                #pragma unroll
                for (int ni = 0; ni < 2; ni++)
                    ldsm_x2t(bf[ni], bB + ks*(16*AT_V_PITCH) + ni*16);
                #pragma unroll
                for (int mi = 0; mi < 3; mi++)
                    #pragma unroll
                    for (int ni = 0; ni < 2; ni++)
                        mma16816(acc[mi][ni], af[mi], bf[ni]);
            }
        }
        __syncthreads();   // all warps done reading V before O overlay

        float* sO = (float*)(sma + AOFF_O);
        int r = lane >> 2, c2 = (lane & 3) * 2;
        #pragma unroll
        for (int mi = 0; mi < 3; mi++)
            #pragma unroll
            for (int ni = 0; ni < 2; ni++) {
                int row = m0 + mi*16 + r, col = cW + ni*8 + c2;
                *(float2*)&sO[row*AT_O_PITCH + col]     = make_float2(acc[mi][ni][0], acc[mi][ni][1]);
                *(float2*)&sO[(row+8)*AT_O_PITCH + col] = make_float2(acc[mi][ni][2], acc[mi][ni][3]);
            }
        __syncthreads();

        for (int i = tid; i < 1536; i += 256) {
            int h = i >> 4, c4 = (i & 15) * 4;
            *(float4*)&Og[(size_t)h*CC + c0 + c4] = *(float4*)&sO[h*AT_O_PITCH + c4];
        }
        __syncthreads();
    }
}

// ---------------- kernel 3: transpose back + residual ------------------------
__global__ __launch_bounds__(256) void out_kernel(const float* __restrict__ x,
                                                  const float* __restrict__ gamma,
                                                  float* __restrict__ out) {
    __shared__ float tile[32][33];
    int c0 = blockIdx.x * 32;
    int w0 = blockIdx.y * 32;
    int bh = blockIdx.z;
    int b = bh / HH, h = bh % HH;
    int tx = threadIdx.x, ty = threadIdx.y;   // 32 x 8
    float gm = gamma[0];
    const float* Ob = g_Ot + (size_t)b * WW * HH * CC;
    #pragma unroll
    for (int i = 0; i < 4; i++) {
        int wl = ty + i*8;
        tile[wl][tx] = Ob[(size_t)((w0 + wl)*HH + h)*CC + c0 + tx];
    }
    __syncthreads();
    size_t base = (size_t)b * CC * PP + (size_t)h * WW;
    #pragma unroll
    for (int i = 0; i < 4; i++) {
        int cl = ty + i*8;
        size_t idx = base + (size_t)(c0 + cl) * PP + w0 + tx;
        out[idx] = gm * tile[tx][cl] + x[idx];
    }
}

// ---------------- launcher ---------------------------------------------------
extern "C" void kernel_launch(void* const* d_in, const int* in_sizes, int n_in,
                              void* d_out, int out_size) {
    const float* x     = (const float*)d_in[0];
    const float* Wq    = (const float*)d_in[1];
    const float* bq    = (const float*)d_in[2];
    const float* Wk    = (const float*)d_in[3];
    const float* bk    = (const float*)d_in[4];
    const float* Wv    = (const float*)d_in[5];
    const float* bv    = (const float*)d_in[6];
    const float* gamma = (const float*)d_in[7];
    float* out = (float*)d_out;

    cudaFuncSetAttribute(qkv_mma_kernel, cudaFuncAttributeMaxDynamicSharedMemorySize, QKV_SMEM);
    cudaFuncSetAttribute(attn_mma_kernel, cudaFuncAttributeMaxDynamicSharedMemorySize, ATT_SMEM);

    prep_kernel<<<(JTOT*CC + 255)/256, 256>>>(Wq, bq, Wk, bk, Wv, bv);
    qkv_mma_kernel<<<dim3(PP/128, 3, BB), 256, QKV_SMEM>>>(x);
    attn_mma_kernel<<<dim3(BB*WW), 256, ATT_SMEM>>>();
    out_kernel<<<dim3(CC/32, WW/32, BB*HH), dim3(32, 8)>>>(x, gamma, out);
}

// round 5
// speedup vs baseline: 1.7669x; 1.1098x over previous
#include <cuda_runtime.h>
#include <cuda_bf16.h>
#include <cstdint>

#define BB 16
#define CC 256
#define HH 96
#define WW 96
#define QKD 64
#define PP (HH*WW)          // 9216
#define JTOT 384

// ---------------- scratch (static device memory; no allocs allowed) ----------
__device__ float g_bcat[JTOT];
__device__ __nv_bfloat16 g_Whi[JTOT*CC];
__device__ __nv_bfloat16 g_Wlo[JTOT*CC];
__device__ __nv_bfloat16 g_xhi[(size_t)BB*CC*PP];   // [b][k][p]
__device__ __nv_bfloat16 g_xlo[(size_t)BB*CC*PP];
__device__ __nv_bfloat16 g_Qhi[(size_t)BB*WW*HH*QKD];  // [b*w*h][q]
__device__ __nv_bfloat16 g_Qlo[(size_t)BB*WW*HH*QKD];
__device__ __nv_bfloat16 g_Khi[(size_t)BB*WW*HH*QKD];
__device__ __nv_bfloat16 g_Klo[(size_t)BB*WW*HH*QKD];
__device__ __nv_bfloat16 g_Vhi[(size_t)BB*WW*HH*CC];   // [b*w*g][c]
__device__ __nv_bfloat16 g_Vlo[(size_t)BB*WW*HH*CC];
__device__ float g_Ot[(size_t)BB*WW*HH*CC];            // [b][w][h][c]

// ---------------- PTX helpers (baseline, sm_103-safe) ------------------------
__device__ __forceinline__ uint32_t smem_u32(const void* p) {
    uint32_t a;
    asm("{ .reg .u64 t; cvta.to.shared.u64 t, %1; cvt.u32.u64 %0, t; }" : "=r"(a) : "l"(p));
    return a;
}
__device__ __forceinline__ void ldsm_x4(uint32_t* r, uint32_t addr) {
    asm volatile("ldmatrix.sync.aligned.m8n8.x4.shared.b16 {%0,%1,%2,%3}, [%4];"
        : "=r"(r[0]), "=r"(r[1]), "=r"(r[2]), "=r"(r[3]) : "r"(addr));
}
__device__ __forceinline__ void ldsm_x2(uint32_t* r, uint32_t addr) {
    asm volatile("ldmatrix.sync.aligned.m8n8.x2.shared.b16 {%0,%1}, [%2];"
        : "=r"(r[0]), "=r"(r[1]) : "r"(addr));
}
__device__ __forceinline__ void ldsm_x2t(uint32_t* r, uint32_t addr) {
    asm volatile("ldmatrix.sync.aligned.m8n8.x2.trans.shared.b16 {%0,%1}, [%2];"
        : "=r"(r[0]), "=r"(r[1]) : "r"(addr));
}
__device__ __forceinline__ void mma16816(float* d, const uint32_t* a, const uint32_t* b) {
    asm volatile("mma.sync.aligned.m16n8k16.row.col.f32.bf16.bf16.f32 "
        "{%0,%1,%2,%3}, {%4,%5,%6,%7}, {%8,%9}, {%0,%1,%2,%3};"
        : "+f"(d[0]), "+f"(d[1]), "+f"(d[2]), "+f"(d[3])
        : "r"(a[0]), "r"(a[1]), "r"(a[2]), "r"(a[3]), "r"(b[0]), "r"(b[1]));
}
__device__ __forceinline__ void cvt_hilo(float4 v, uint2& hi, uint2& lo) {
    __nv_bfloat162 h0 = __float22bfloat162_rn(make_float2(v.x, v.y));
    __nv_bfloat162 h1 = __float22bfloat162_rn(make_float2(v.z, v.w));
    float2 f0 = __bfloat1622float2(h0), f1 = __bfloat1622float2(h1);
    __nv_bfloat162 l0 = __float22bfloat162_rn(make_float2(v.x - f0.x, v.y - f0.y));
    __nv_bfloat162 l1 = __float22bfloat162_rn(make_float2(v.z - f1.x, v.w - f1.y));
    hi = make_uint2(*(uint32_t*)&h0, *(uint32_t*)&h1);
    lo = make_uint2(*(uint32_t*)&l0, *(uint32_t*)&l1);
}
#define CP_ASYNC16(dst, src) \
    asm volatile("cp.async.cg.shared.global [%0], [%1], 16;" :: "r"(dst), "l"(src))
#define CP_COMMIT() asm volatile("cp.async.commit_group;" ::: "memory")
#define CP_WAIT1()  asm volatile("cp.async.wait_group 1;" ::: "memory")

// ---------------- kernel 0a: weight concat + bf16 split ----------------------
__global__ void prep_kernel(const float* __restrict__ Wq, const float* __restrict__ bq,
                            const float* __restrict__ Wk, const float* __restrict__ bk,
                            const float* __restrict__ Wv, const float* __restrict__ bv) {
    int i = blockIdx.x * blockDim.x + threadIdx.x;
    if (i < JTOT*CC) {
        int j = i / CC, k = i % CC;
        float v;
        if (j < 64)       v = Wq[j*CC + k];
        else if (j < 128) v = Wk[(j-64)*CC + k];
        else              v = Wv[(j-128)*CC + k];
        __nv_bfloat16 h = __float2bfloat16(v);
        g_Whi[i] = h;
        g_Wlo[i] = __float2bfloat16(v - __bfloat162float(h));
    }
    if (i < JTOT) {
        g_bcat[i] = (i < 64) ? bq[i] : (i < 128) ? bk[i-64] : bv[i-128];
    }
}

// ---------------- kernel 0b: split x into bf16 hi/lo -------------------------
__global__ __launch_bounds__(256) void xsplit_kernel(const float* __restrict__ x) {
    size_t idx = (size_t)blockIdx.x * 256 + threadIdx.x;   // float4 index
    float4 v = *(const float4*)(x + idx*4);
    uint2 hi, lo; cvt_hilo(v, hi, lo);
    *(uint2*)(g_xhi + idx*4) = hi;
    *(uint2*)(g_xlo + idx*4) = lo;
}

// ---------------- kernel 1: QKV projection, resident-B + cp.async ------------
// Per CTA: 64-pixel tile, all 384 j. B (x hi/lo, 256k x 64p) resident.
// A (W hi/lo, 128j x 64k) double-buffered cp.async per (jt, chunk).
#define BP 144              // B row pitch bytes (72 bf16, 16B-aligned)
#define AP 144              // A row pitch bytes
#define OFF_BH   0
#define OFF_BL   36864
#define OFF_A0H  73728
#define OFF_A0L  92160
#define OFF_A1H  110592
#define OFF_A1L  129024
#define OFF_STG  147456     // 64 x 132 floats = 33792 B
#define OFF_BIAS 181248
#define QKV_SMEM 182784

__global__ __launch_bounds__(256) void qkv_mma_kernel() {
    extern __shared__ __align__(1024) char smq[];
    uint32_t sb = smem_u32(smq);
    int tid = threadIdx.x;
    int wid = tid >> 5, lane = tid & 31;
    int pBase = blockIdx.x * 64;
    int bz = blockIdx.y;
    int warpM = wid & 3, warpN = wid >> 2;       // 4 x 2 warp grid
    uint32_t jW = warpM * 32, pW = warpN * 32;

    for (int t = tid; t < JTOT; t += 256)
        *(float*)(smq + OFF_BIAS + t*4) = g_bcat[t];

    // ---- B: all 256 k rows, hi+lo, via cp.async (group 0, with A0)
    {
        const __nv_bfloat16* xh = g_xhi + (size_t)bz * CC * PP;
        const __nv_bfloat16* xl = g_xlo + (size_t)bz * CC * PP;
        for (int t = tid; t < 2048; t += 256) {
            int k = t >> 3, sg = t & 7;
            const __nv_bfloat16* s = xh + (size_t)k * PP + pBase + sg*8;
            CP_ASYNC16(sb + OFF_BH + k*BP + sg*16, s);
            s = xl + (size_t)k * PP + pBase + sg*8;
            CP_ASYNC16(sb + OFF_BL + k*BP + sg*16, s);
        }
    }
    // ---- A(it=0) into buf0
    {
        for (int t = tid; t < 1024; t += 256) {
            int j = t >> 3, sg = t & 7;
            CP_ASYNC16(sb + OFF_A0H + j*AP + sg*16, g_Whi + j*CC + sg*8);
            CP_ASYNC16(sb + OFF_A0L + j*AP + sg*16, g_Wlo + j*CC + sg*8);
        }
    }
    CP_COMMIT();

    uint32_t aOff = (lane & 15) * AP + (lane >> 4) * 16 + jW * AP;
    uint32_t bOff = (lane & 15) * BP + pW * 2;
    float* stg = (float*)(smq + OFF_STG);
    int it = 0;

    for (int jt = 0; jt < 3; jt++) {
        float acc[2][4][4] = {};
        for (int ch = 0; ch < 4; ch++) {
            int buf = it & 1;
            // prefetch next A stage
            if (it < 11) {
                int nit = it + 1;
                int njt = nit >> 2, nch = nit & 3;
                uint32_t dH = sb + ((nit & 1) ? OFF_A1H : OFF_A0H);
                uint32_t dL = sb + ((nit & 1) ? OFF_A1L : OFF_A0L);
                const __nv_bfloat16* sH = g_Whi + (njt*128)*CC + nch*64;
                const __nv_bfloat16* sL = g_Wlo + (njt*128)*CC + nch*64;
                for (int t = tid; t < 1024; t += 256) {
                    int j = t >> 3, sg = t & 7;
                    CP_ASYNC16(dH + j*AP + sg*16, sH + j*CC + sg*8);
                    CP_ASYNC16(dL + j*AP + sg*16, sL + j*CC + sg*8);
                }
            }
            CP_COMMIT();
            CP_WAIT1();
            __syncthreads();

            uint32_t aHB = sb + (buf ? OFF_A1H : OFF_A0H) + aOff;
            uint32_t aLB = sb + (buf ? OFF_A1L : OFF_A0L) + aOff;
            #pragma unroll
            for (int pass = 0; pass < 3; pass++) {
                uint32_t aB = (pass == 2) ? aLB : aHB;
                uint32_t bB = sb + ((pass == 1) ? OFF_BL : OFF_BH) + bOff;
                #pragma unroll
                for (int ksc = 0; ksc < 4; ksc++) {
                    int ks16 = ch*4 + ksc;
                    uint32_t af[2][4], bf[4][2];
                    #pragma unroll
                    for (int mi = 0; mi < 2; mi++)
                        ldsm_x4(af[mi], aB + mi*(16*AP) + ksc*32);
                    #pragma unroll
                    for (int ni = 0; ni < 4; ni++)
                        ldsm_x2t(bf[ni], bB + ks16*(16*BP) + ni*16);
                    #pragma unroll
                    for (int mi = 0; mi < 2; mi++)
                        #pragma unroll
                        for (int ni = 0; ni < 4; ni++)
                            mma16816(acc[mi][ni], af[mi], bf[ni]);
                }
            }
            __syncthreads();
            it++;
        }

        // ---- epilogue for this j-tile: frags -> stage[p][j] -> bf16 stores
        {
            int r = lane >> 2, c2 = (lane & 3) * 2;
            #pragma unroll
            for (int mi = 0; mi < 2; mi++)
                #pragma unroll
                for (int ni = 0; ni < 4; ni++) {
                    int j = jW + mi*16 + r;
                    int p = pW + ni*8 + c2;
                    stg[p*132 + j]         = acc[mi][ni][0];
                    stg[(p+1)*132 + j]     = acc[mi][ni][1];
                    stg[p*132 + j + 8]     = acc[mi][ni][2];
                    stg[(p+1)*132 + j + 8] = acc[mi][ni][3];
                }
        }
        __syncthreads();
        const float* sBias = (const float*)(smq + OFF_BIAS) + jt*128;
        for (int idx = tid; idx < 64*128; idx += 256) {
            int pl = idx >> 7, j = idx & 127;
            float val = stg[pl*132 + j] + sBias[j];
            int p = pBase + pl;
            int h = p / WW, w = p - h*WW;
            size_t col = (size_t)(bz*WW + w)*HH + h;
            __nv_bfloat16 hi = __float2bfloat16(val);
            __nv_bfloat16 lo = __float2bfloat16(val - __bfloat162float(hi));
            if (jt == 0) {
                if (j < 64) { g_Qhi[col*QKD + j] = hi;      g_Qlo[col*QKD + j] = lo; }
                else        { g_Khi[col*QKD + j-64] = hi;   g_Klo[col*QKD + j-64] = lo; }
            } else {
                size_t o = col*CC + (jt-1)*128 + j;
                g_Vhi[o] = hi; g_Vlo[o] = lo;
            }
        }
        __syncthreads();
    }
}

// ---------------- kernel 2: per-(b,w) column attention, bf16x3 warp MMA ------
#define AT_QK_PITCH 144
#define AT_S_PITCH  100
#define AT_A_PITCH  208
#define AT_V_PITCH  144
#define AT_O_PITCH  68
#define AOFF_QH 0
#define AOFF_QL 13824
#define AOFF_KH 27648
#define AOFF_KL 41472
#define AOFF_AH 0
#define AOFF_AL 19968
#define AOFF_S  55296
#define AOFF_VH 55296
#define AOFF_VL 69120
#define AOFF_O  55296
#define ATT_SMEM 93696

__global__ __launch_bounds__(256) void attn_mma_kernel() {
    extern __shared__ __align__(128) char sma[];
    uint32_t sb = smem_u32(sma);
    int tid = threadIdx.x;
    int wid = tid >> 5, lane = tid & 31;
    int bw = blockIdx.x;

    // ---- stage Q,K (pure copies of prepared bf16 hi/lo)
    {
        const __nv_bfloat16* Qh = g_Qhi + (size_t)bw * HH * QKD;
        const __nv_bfloat16* Ql = g_Qlo + (size_t)bw * HH * QKD;
        const __nv_bfloat16* Kh = g_Khi + (size_t)bw * HH * QKD;
        const __nv_bfloat16* Kl = g_Klo + (size_t)bw * HH * QKD;
        for (int i = tid; i < 768; i += 256) {
            int h = i >> 3, sg = i & 7;
            uint32_t so = (uint32_t)(h*AT_QK_PITCH + sg*16);
            int go = h*QKD + sg*8;
            *(uint4*)(sma + AOFF_QH + so) = *(const uint4*)(Qh + go);
            *(uint4*)(sma + AOFF_QL + so) = *(const uint4*)(Ql + go);
            *(uint4*)(sma + AOFF_KH + so) = *(const uint4*)(Kh + go);
            *(uint4*)(sma + AOFF_KL + so) = *(const uint4*)(Kl + go);
        }
    }
    __syncthreads();

    int warpM = wid & 1, warpN = wid >> 1;
    int m0 = warpM * 48;

    // ---- scores: S[h,g], warp tile 48m x 24n
    {
        int n0 = warpN * 24;
        float acc[3][3][4] = {};
        uint32_t aOff = (uint32_t)((m0 + (lane & 15))*AT_QK_PITCH + (lane >> 4)*16);
        uint32_t bOff = (uint32_t)((n0 + (lane & 7))*AT_QK_PITCH + ((lane >> 3) & 1)*16);
        #pragma unroll
        for (int pass = 0; pass < 3; pass++) {
            uint32_t aB = sb + ((pass == 2) ? AOFF_QL : AOFF_QH) + aOff;
            uint32_t bB = sb + ((pass == 1) ? AOFF_KL : AOFF_KH) + bOff;
            #pragma unroll
            for (int ks = 0; ks < 4; ks++) {
                uint32_t af[3][4], bf[3][2];
                #pragma unroll
                for (int mi = 0; mi < 3; mi++)
                    ldsm_x4(af[mi], aB + mi*(16*AT_QK_PITCH) + ks*32);
                #pragma unroll
                for (int nj = 0; nj < 3; nj++)
                    ldsm_x2(bf[nj], bB + nj*(8*AT_QK_PITCH) + ks*32);
                #pragma unroll
                for (int mi = 0; mi < 3; mi++)
                    #pragma unroll
                    for (int nj = 0; nj < 3; nj++)
                        mma16816(acc[mi][nj], af[mi], bf[nj]);
            }
        }
        float* sS = (float*)(sma + AOFF_S);
        int r = lane >> 2, c2 = (lane & 3) * 2;
        #pragma unroll
        for (int mi = 0; mi < 3; mi++)
            #pragma unroll
            for (int nj = 0; nj < 3; nj++) {
                int row = m0 + mi*16 + r, col = n0 + nj*8 + c2;
                *(float2*)&sS[row*AT_S_PITCH + col]     = make_float2(acc[mi][nj][0], acc[mi][nj][1]);
                *(float2*)&sS[(row+8)*AT_S_PITCH + col] = make_float2(acc[mi][nj][2], acc[mi][nj][3]);
            }
    }
    __syncthreads();

    // ---- softmax + emit A as bf16 hi/lo
    {
        float* sS = (float*)(sma + AOFF_S);
        __nv_bfloat16* sAh = (__nv_bfloat16*)(sma + AOFF_AH);
        __nv_bfloat16* sAl = (__nv_bfloat16*)(sma + AOFF_AL);
        for (int r = 0; r < 12; r++) {
            int h = wid*12 + r;
            float v0 = sS[h*AT_S_PITCH + lane];
            float v1 = sS[h*AT_S_PITCH + 32 + lane];
            float v2 = sS[h*AT_S_PITCH + 64 + lane];
            float m = fmaxf(v0, fmaxf(v1, v2));
            #pragma unroll
            for (int o = 16; o > 0; o >>= 1) m = fmaxf(m, __shfl_xor_sync(0xffffffffu, m, o));
            float e0 = __expf(v0 - m), e1 = __expf(v1 - m), e2 = __expf(v2 - m);
            float s = e0 + e1 + e2;
            #pragma unroll
            for (int o = 16; o > 0; o >>= 1) s += __shfl_xor_sync(0xffffffffu, s, o);
            float inv = 1.0f / s;
            float a0 = e0*inv, a1 = e1*inv, a2 = e2*inv;
            __nv_bfloat16 h0 = __float2bfloat16(a0);
            __nv_bfloat16 h1 = __float2bfloat16(a1);
            __nv_bfloat16 h2 = __float2bfloat16(a2);
            sAh[h*104 + lane]      = h0;
            sAh[h*104 + 32 + lane] = h1;
            sAh[h*104 + 64 + lane] = h2;
            sAl[h*104 + lane]      = __float2bfloat16(a0 - __bfloat162float(h0));
            sAl[h*104 + 32 + lane] = __float2bfloat16(a1 - __bfloat162float(h1));
            sAl[h*104 + 64 + lane] = __float2bfloat16(a2 - __bfloat162float(h2));
        }
    }
    __syncthreads();

    // ---- AV: c chunks of 64, warp tile 48m x 16n
    const __nv_bfloat16* Vh = g_Vhi + (size_t)bw * HH * CC;
    const __nv_bfloat16* Vl = g_Vlo + (size_t)bw * HH * CC;
    float* Og = g_Ot + (size_t)bw * HH * CC;
    int cW = warpN * 16;
    uint32_t aOff = (uint32_t)((m0 + (lane & 15))*AT_A_PITCH + (lane >> 4)*16);
    uint32_t bOff = (uint32_t)((lane & 15)*AT_V_PITCH + cW*2);

    for (int c0 = 0; c0 < CC; c0 += 64) {
        for (int i = tid; i < 768; i += 256) {
            int g = i >> 3, sg = i & 7;
            uint32_t so = (uint32_t)(g*AT_V_PITCH + sg*16);
            size_t go = (size_t)g*CC + c0 + sg*8;
            *(uint4*)(sma + AOFF_VH + so) = *(const uint4*)(Vh + go);
            *(uint4*)(sma + AOFF_VL + so) = *(const uint4*)(Vl + go);
        }
        __syncthreads();

        float acc[3][2][4] = {};
        #pragma unroll
        for (int pass = 0; pass < 3; pass++) {
            uint32_t aB = sb + ((pass == 2) ? AOFF_AL : AOFF_AH) + aOff;
            uint32_t bB = sb + ((pass == 1) ? AOFF_VL : AOFF_VH) + bOff;
            #pragma unroll
            for (int ks = 0; ks < 6; ks++) {
                uint32_t af[3][4], bf[2][2];
                #pragma unroll
                for (int mi = 0; mi < 3; mi++)
                    ldsm_x4(af[mi], aB + mi*(16*AT_A_PITCH) + ks*32);
                #pragma unroll
                for (int ni = 0; ni < 2; ni++)
                    ldsm_x2t(bf[ni], bB + ks*(16*AT_V_PITCH) + ni*16);
                #pragma unroll
                for (int mi = 0; mi < 3; mi++)
                    #pragma unroll
                    for (int ni = 0; ni < 2; ni++)
                        mma16816(acc[mi][ni], af[mi], bf[ni]);
            }
        }
        __syncthreads();

        float* sO = (float*)(sma + AOFF_O);
        int r = lane >> 2, c2 = (lane & 3) * 2;
        #pragma unroll
        for (int mi = 0; mi < 3; mi++)
            #pragma unroll
            for (int ni = 0; ni < 2; ni++) {
                int row = m0 + mi*16 + r, col = cW + ni*8 + c2;
                *(float2*)&sO[row*AT_O_PITCH + col]     = make_float2(acc[mi][ni][0], acc[mi][ni][1]);
                *(float2*)&sO[(row+8)*AT_O_PITCH + col] = make_float2(acc[mi][ni][2], acc[mi][ni][3]);
            }
        __syncthreads();

        for (int i = tid; i < 1536; i += 256) {
            int h = i >> 4, c4 = (i & 15) * 4;
            *(float4*)&Og[(size_t)h*CC + c0 + c4] = *(float4*)&sO[h*AT_O_PITCH + c4];
        }
        __syncthreads();
    }
}

// ---------------- kernel 3: transpose back + residual ------------------------
__global__ __launch_bounds__(256) void out_kernel(const float* __restrict__ x,
                                                  const float* __restrict__ gamma,
                                                  float* __restrict__ out) {
    __shared__ float tile[32][33];
    int c0 = blockIdx.x * 32;
    int w0 = blockIdx.y * 32;
    int bh = blockIdx.z;
    int b = bh / HH, h = bh % HH;
    int tx = threadIdx.x, ty = threadIdx.y;
    float gm = gamma[0];
    const float* Ob = g_Ot + (size_t)b * WW * HH * CC;
    #pragma unroll
    for (int i = 0; i < 4; i++) {
        int wl = ty + i*8;
        tile[wl][tx] = Ob[(size_t)((w0 + wl)*HH + h)*CC + c0 + tx];
    }
    __syncthreads();
    size_t base = (size_t)b * CC * PP + (size_t)h * WW;
    #pragma unroll
    for (int i = 0; i < 4; i++) {
        int cl = ty + i*8;
        size_t idx = base + (size_t)(c0 + cl) * PP + w0 + tx;
        out[idx] = gm * tile[tx][cl] + x[idx];
    }
}

// ---------------- launcher ---------------------------------------------------
extern "C" void kernel_launch(void* const* d_in, const int* in_sizes, int n_in,
                              void* d_out, int out_size) {
    const float* x     = (const float*)d_in[0];
    const float* Wq    = (const float*)d_in[1];
    const float* bq    = (const float*)d_in[2];
    const float* Wk    = (const float*)d_in[3];
    const float* bk    = (const float*)d_in[4];
    const float* Wv    = (const float*)d_in[5];
    const float* bv    = (const float*)d_in[6];
    const float* gamma = (const float*)d_in[7];
    float* out = (float*)d_out;

    cudaFuncSetAttribute(qkv_mma_kernel, cudaFuncAttributeMaxDynamicSharedMemorySize, QKV_SMEM);
    cudaFuncSetAttribute(attn_mma_kernel, cudaFuncAttributeMaxDynamicSharedMemorySize, ATT_SMEM);

    prep_kernel<<<(JTOT*CC + 255)/256, 256>>>(Wq, bq, Wk, bk, Wv, bv);
    xsplit_kernel<<<(int)((size_t)BB*CC*PP/4/256), 256>>>(x);
    qkv_mma_kernel<<<dim3(PP/64, BB), 256, QKV_SMEM>>>();
    attn_mma_kernel<<<dim3(BB*WW), 256, ATT_SMEM>>>();
    out_kernel<<<dim3(CC/32, WW/32, BB*HH), dim3(32, 8)>>>(x, gamma, out);
}

// round 6
// speedup vs baseline: 2.1310x; 1.2061x over previous
#include <cuda_runtime.h>
#include <cuda_fp16.h>
#include <cstdint>

#define BB 16
#define CC 256
#define HH 96
#define WW 96
#define QKD 64
#define PP (HH*WW)          // 9216
#define JTOT 384

// ---------------- scratch (static device memory; no allocs allowed) ----------
__device__ float g_bcat[JTOT];
__device__ __half g_Whi[JTOT*CC];
__device__ __half g_Wlo[JTOT*CC];
__device__ __half g_xhi[(size_t)BB*CC*PP];          // [b][k][p]
__device__ __half g_xlo[(size_t)BB*CC*PP];
__device__ __half g_Qhi[(size_t)BB*WW*HH*QKD];      // [b*w*h][q]
__device__ __half g_Qlo[(size_t)BB*WW*HH*QKD];
__device__ __half g_Khi[(size_t)BB*WW*HH*QKD];
__device__ __half g_Klo[(size_t)BB*WW*HH*QKD];
__device__ __half g_Vhi[(size_t)BB*WW*HH*CC];       // [b*w*g][c]
__device__ __half g_Vlo[(size_t)BB*WW*HH*CC];
__device__ float g_Ot[(size_t)BB*WW*HH*CC];         // [b][w][h][c]

// ---------------- PTX helpers (baseline, sm_103-safe) ------------------------
__device__ __forceinline__ uint32_t smem_u32(const void* p) {
    uint32_t a;
    asm("{ .reg .u64 t; cvta.to.shared.u64 t, %1; cvt.u32.u64 %0, t; }" : "=r"(a) : "l"(p));
    return a;
}
__device__ __forceinline__ void ldsm_x4(uint32_t* r, uint32_t addr) {
    asm volatile("ldmatrix.sync.aligned.m8n8.x4.shared.b16 {%0,%1,%2,%3}, [%4];"
        : "=r"(r[0]), "=r"(r[1]), "=r"(r[2]), "=r"(r[3]) : "r"(addr));
}
__device__ __forceinline__ void ldsm_x2(uint32_t* r, uint32_t addr) {
    asm volatile("ldmatrix.sync.aligned.m8n8.x2.shared.b16 {%0,%1}, [%2];"
        : "=r"(r[0]), "=r"(r[1]) : "r"(addr));
}
__device__ __forceinline__ void ldsm_x2t(uint32_t* r, uint32_t addr) {
    asm volatile("ldmatrix.sync.aligned.m8n8.x2.trans.shared.b16 {%0,%1}, [%2];"
        : "=r"(r[0]), "=r"(r[1]) : "r"(addr));
}
__device__ __forceinline__ void mma_h(float* d, const uint32_t* a, const uint32_t* b) {
    asm volatile("mma.sync.aligned.m16n8k16.row.col.f32.f16.f16.f32 "
        "{%0,%1,%2,%3}, {%4,%5,%6,%7}, {%8,%9}, {%0,%1,%2,%3};"
        : "+f"(d[0]), "+f"(d[1]), "+f"(d[2]), "+f"(d[3])
        : "r"(a[0]), "r"(a[1]), "r"(a[2]), "r"(a[3]), "r"(b[0]), "r"(b[1]));
}
__device__ __forceinline__ void cvt_hilo_h(float4 v, uint2& hi, uint2& lo) {
    __half2 h0 = __float22half2_rn(make_float2(v.x, v.y));
    __half2 h1 = __float22half2_rn(make_float2(v.z, v.w));
    float2 f0 = __half22float2(h0), f1 = __half22float2(h1);
    __half2 l0 = __float22half2_rn(make_float2(v.x - f0.x, v.y - f0.y));
    __half2 l1 = __float22half2_rn(make_float2(v.z - f1.x, v.w - f1.y));
    hi = make_uint2(*(uint32_t*)&h0, *(uint32_t*)&h1);
    lo = make_uint2(*(uint32_t*)&l0, *(uint32_t*)&l1);
}
#define CP_ASYNC16(dst, src) \
    asm volatile("cp.async.cg.shared.global [%0], [%1], 16;" :: "r"(dst), "l"(src))
#define CP_COMMIT() asm volatile("cp.async.commit_group;" ::: "memory")
#define CP_WAIT0()  asm volatile("cp.async.wait_group 0;" ::: "memory")

// ---------------- kernel 0a: weight concat + fp16 split ----------------------
__global__ void prep_kernel(const float* __restrict__ Wq, const float* __restrict__ bq,
                            const float* __restrict__ Wk, const float* __restrict__ bk,
                            const float* __restrict__ Wv, const float* __restrict__ bv) {
    int i = blockIdx.x * blockDim.x + threadIdx.x;
    if (i < JTOT*CC) {
        int j = i / CC, k = i % CC;
        float v;
        if (j < 64)       v = Wq[j*CC + k];
        else if (j < 128) v = Wk[(j-64)*CC + k];
        else              v = Wv[(j-128)*CC + k];
        __half h = __float2half_rn(v);
        g_Whi[i] = h;
        g_Wlo[i] = __float2half_rn(v - __half2float(h));
    }
    if (i < JTOT) {
        g_bcat[i] = (i < 64) ? bq[i] : (i < 128) ? bk[i-64] : bv[i-128];
    }
}

// ---------------- kernel 0b: split x into fp16 hi/lo -------------------------
__global__ __launch_bounds__(256) void xsplit_kernel(const float* __restrict__ x) {
    size_t idx = (size_t)blockIdx.x * 256 + threadIdx.x;
    float4 v = *(const float4*)(x + idx*4);
    uint2 hi, lo; cvt_hilo_h(v, hi, lo);
    *(uint2*)(g_xhi + idx*4) = hi;
    *(uint2*)(g_xlo + idx*4) = lo;
}

// ---------------- kernel 1: QKV projection (fp16 multi-pass warp MMA) --------
// C[j,p] = sum_k W[j,k]*x[b,k,p] + bias[j]; p-tile 64, j-tiles of 64 (6).
// B (x hi/lo 256k x 64p) resident; rows 128B, XOR-swizzled. A double-buffered.
// jt 0,1 (Q,K): 3 passes. jt 2..5 (V): 2 passes (drop Whi*xlo).
#define OFF_BH   0
#define OFF_BL   32768
#define OFF_A    65536       // buf0: hi@0 lo@8192; buf1: hi@16384 lo@24576
#define OFF_STG  65536       // overlays A in epilogue (16.9KB <= 32KB)
#define OFF_BIAS 98304
#define QKV_SMEM 99840
#define STGP 66

__global__ __launch_bounds__(256) void qkv_mma_kernel() {
    extern __shared__ __align__(128) char smq[];
    uint32_t sb = smem_u32(smq);
    int tid = threadIdx.x, wid = tid >> 5, lane = tid & 31;
    int pBase = blockIdx.x * 64;
    int bz = blockIdx.y;
    int warpM = wid & 1, warpN = wid >> 1;   // 2 x 4
    int jW = warpM * 32, pW = warpN * 16;

    for (int t = tid; t < JTOT; t += 256)
        *(float*)(smq + OFF_BIAS + t*4) = g_bcat[t];

    // B resident (hi+lo), swizzled 128B rows
    {
        const __half* xh = g_xhi + (size_t)bz*CC*PP;
        const __half* xl = g_xlo + (size_t)bz*CC*PP;
        for (int t = tid; t < 2048; t += 256) {
            int k = t >> 3, sg = t & 7;
            uint32_t sw = (uint32_t)(k*128 + ((sg ^ (k & 7))*16));
            CP_ASYNC16(sb + OFF_BH + sw, xh + (size_t)k*PP + pBase + sg*8);
            CP_ASYNC16(sb + OFF_BL + sw, xl + (size_t)k*PP + pBase + sg*8);
        }
    }
    // A(jt0, ch0) -> buf0
    for (int t = tid; t < 512; t += 256) {
        int j = t >> 3, sg = t & 7;
        uint32_t sw = (uint32_t)(j*128 + ((sg ^ (j & 7))*16));
        CP_ASYNC16(sb + OFF_A + sw,        g_Whi + j*CC + sg*8);
        CP_ASYNC16(sb + OFF_A + 8192 + sw, g_Wlo + j*CC + sg*8);
    }
    CP_COMMIT();

    int rA   = lane & 15;
    int swzA = rA & 7;
    int aseg = lane >> 4;
    int swzB = lane & 7;
    int bseg = (pW >> 3);     // warpN*2

    for (int jt = 0; jt < 6; jt++) {
        float acc[2][2][4] = {};
        bool threepass = (jt < 2);

        for (int ch = 0; ch < 4; ch++) {
            CP_WAIT0();
            __syncthreads();
            if (ch < 3) {
                uint32_t dst = sb + OFF_A + (uint32_t)(((ch+1) & 1) * 16384);
                const __half* sH = g_Whi + (jt*64)*CC + (ch+1)*64;
                const __half* sL = g_Wlo + (jt*64)*CC + (ch+1)*64;
                for (int t = tid; t < 512; t += 256) {
                    int j = t >> 3, sg = t & 7;
                    uint32_t sw = (uint32_t)(j*128 + ((sg ^ (j & 7))*16));
                    CP_ASYNC16(dst + sw,        sH + j*CC + sg*8);
                    CP_ASYNC16(dst + 8192 + sw, sL + j*CC + sg*8);
                }
                CP_COMMIT();
            }
            uint32_t aBufH = sb + OFF_A + (uint32_t)((ch & 1) * 16384);
            uint32_t aBufL = aBufH + 8192;
            #pragma unroll
            for (int pass = 0; pass < 3; pass++) {
                if (pass == 1 && !threepass) continue;
                uint32_t aB = (pass == 2) ? aBufL : aBufH;
                uint32_t bB = sb + ((pass == 1) ? OFF_BL : OFF_BH);
                #pragma unroll
                for (int ksc = 0; ksc < 4; ksc++) {
                    int ks16 = ch*4 + ksc;
                    uint32_t af[2][4], bf[2][2];
                    #pragma unroll
                    for (int mi = 0; mi < 2; mi++) {
                        int row = jW + rA + mi*16;
                        ldsm_x4(af[mi], aB + (uint32_t)(row*128 + (((ksc*2 + aseg) ^ swzA)*16)));
                    }
                    #pragma unroll
                    for (int ni = 0; ni < 2; ni++) {
                        int row = ks16*16 + rA;
                        ldsm_x2t(bf[ni], bB + (uint32_t)(row*128 + (((bseg + ni) ^ swzB)*16)));
                    }
                    #pragma unroll
                    for (int mi = 0; mi < 2; mi++)
                        #pragma unroll
                        for (int ni = 0; ni < 2; ni++)
                            mma_h(acc[mi][ni], af[mi], bf[ni]);
                }
            }
        }
        __syncthreads();   // MMA done; A bufs dead -> stage overlay safe

        float* stg = (float*)(smq + OFF_STG);
        {
            int r = lane >> 2, c2 = (lane & 3) * 2;
            #pragma unroll
            for (int mi = 0; mi < 2; mi++)
                #pragma unroll
                for (int ni = 0; ni < 2; ni++) {
                    int j = jW + mi*16 + r;
                    int p = pW + ni*8 + c2;
                    stg[p*STGP + j]         = acc[mi][ni][0];
                    stg[(p+1)*STGP + j]     = acc[mi][ni][1];
                    stg[p*STGP + j + 8]     = acc[mi][ni][2];
                    stg[(p+1)*STGP + j + 8] = acc[mi][ni][3];
                }
        }
        __syncthreads();

        const float* sBias = (const float*)(smq + OFF_BIAS) + jt*64;
        for (int idx = tid; idx < 2048; idx += 256) {
            int pl = idx >> 5, j = (idx & 31) * 2;
            float v0 = stg[pl*STGP + j]     + sBias[j];
            float v1 = stg[pl*STGP + j + 1] + sBias[j + 1];
            __half h0 = __float2half_rn(v0), h1 = __float2half_rn(v1);
            __half l0 = __float2half_rn(v0 - __half2float(h0));
            __half l1 = __float2half_rn(v1 - __half2float(h1));
            __half2 hh = __halves2half2(h0, h1), ll = __halves2half2(l0, l1);
            int p = pBase + pl;
            int h = p / WW, w = p - h*WW;
            size_t col = (size_t)(bz*WW + w)*HH + h;
            if (jt == 0) {
                *(__half2*)(g_Qhi + col*QKD + j) = hh;
                *(__half2*)(g_Qlo + col*QKD + j) = ll;
            } else if (jt == 1) {
                *(__half2*)(g_Khi + col*QKD + j) = hh;
                *(__half2*)(g_Klo + col*QKD + j) = ll;
            } else {
                size_t o = col*CC + (jt-2)*64 + j;
                *(__half2*)(g_Vhi + o) = hh;
                *(__half2*)(g_Vlo + o) = ll;
            }
        }
        __syncthreads();   // stage dead

        if (jt < 5) {
            const __half* sH = g_Whi + ((jt+1)*64)*CC;
            const __half* sL = g_Wlo + ((jt+1)*64)*CC;
            for (int t = tid; t < 512; t += 256) {
                int j = t >> 3, sg = t & 7;
                uint32_t sw = (uint32_t)(j*128 + ((sg ^ (j & 7))*16));
                CP_ASYNC16(sb + OFF_A + sw,        sH + j*CC + sg*8);
                CP_ASYNC16(sb + OFF_A + 8192 + sw, sL + j*CC + sg*8);
            }
            CP_COMMIT();
        }
    }
}

// ---------------- kernel 2: per-(b,w) column attention (fp16 warp MMA) -------
// Q/K: swizzled 128B rows (12288 each). S fp32 pitch 100.
// A(attn): fp16 single, pitch 208B (overlays Q). V hi/lo swizzled (overlays S).
#define AOFF_QH 0
#define AOFF_QL 12288
#define AOFF_KH 24576
#define AOFF_KL 36864
#define AOFF_S  49152      // 96 x 100 fp32 = 38400
#define AOFF_A  0          // 96 x 208B = 19968
#define AOFF_VH 49152
#define AOFF_VL 61440
#define AOFF_O  73728      // 96 x 68 fp32 = 26112
#define ATT_SMEM 99840
#define APITCH 208

__global__ __launch_bounds__(256) void attn_mma_kernel() {
    extern __shared__ __align__(128) char sma[];
    uint32_t sb = smem_u32(sma);
    int tid = threadIdx.x, wid = tid >> 5, lane = tid & 31;
    int bw = blockIdx.x;
    int swz = lane & 7;

    // ---- stage Q,K (swizzled copies)
    {
        const __half* Qh = g_Qhi + (size_t)bw*HH*QKD;
        const __half* Ql = g_Qlo + (size_t)bw*HH*QKD;
        const __half* Kh = g_Khi + (size_t)bw*HH*QKD;
        const __half* Kl = g_Klo + (size_t)bw*HH*QKD;
        for (int i = tid; i < 768; i += 256) {
            int h = i >> 3, sg = i & 7;
            uint32_t sw = (uint32_t)(h*128 + ((sg ^ (h & 7))*16));
            int go = h*QKD + sg*8;
            *(uint4*)(sma + AOFF_QH + sw) = *(const uint4*)(Qh + go);
            *(uint4*)(sma + AOFF_QL + sw) = *(const uint4*)(Ql + go);
            *(uint4*)(sma + AOFF_KH + sw) = *(const uint4*)(Kh + go);
            *(uint4*)(sma + AOFF_KL + sw) = *(const uint4*)(Kl + go);
        }
    }
    __syncthreads();

    int warpM = wid & 1, warpN = wid >> 1;
    int m0 = warpM * 48;

    // ---- scores: S[h,g], warp tile 48m x 24n, 3 passes
    {
        int n0 = warpN * 24;
        float acc[3][3][4] = {};
        #pragma unroll
        for (int pass = 0; pass < 3; pass++) {
            uint32_t aB = sb + ((pass == 2) ? AOFF_QL : AOFF_QH);
            uint32_t bB = sb + ((pass == 1) ? AOFF_KL : AOFF_KH);
            #pragma unroll
            for (int ks = 0; ks < 4; ks++) {
                uint32_t af[3][4], bf[3][2];
                #pragma unroll
                for (int mi = 0; mi < 3; mi++) {
                    int row = m0 + (lane & 15) + mi*16;
                    ldsm_x4(af[mi], aB + (uint32_t)(row*128 + (((ks*2 + (lane >> 4)) ^ swz)*16)));
                }
                #pragma unroll
                for (int nj = 0; nj < 3; nj++) {
                    int row = n0 + nj*8 + (lane & 7);
                    ldsm_x2(bf[nj], bB + (uint32_t)(row*128 + (((ks*2 + ((lane >> 3) & 1)) ^ swz)*16)));
                }
                #pragma unroll
                for (int mi = 0; mi < 3; mi++)
                    #pragma unroll
                    for (int nj = 0; nj < 3; nj++)
                        mma_h(acc[mi][nj], af[mi], bf[nj]);
            }
        }
        float* sS = (float*)(sma + AOFF_S);
        int r = lane >> 2, c2 = (lane & 3) * 2;
        #pragma unroll
        for (int mi = 0; mi < 3; mi++)
            #pragma unroll
            for (int nj = 0; nj < 3; nj++) {
                int row = m0 + mi*16 + r, col = n0 + nj*8 + c2;
                *(float2*)&sS[row*100 + col]     = make_float2(acc[mi][nj][0], acc[mi][nj][1]);
                *(float2*)&sS[(row+8)*100 + col] = make_float2(acc[mi][nj][2], acc[mi][nj][3]);
            }
    }
    __syncthreads();

    // ---- softmax + emit A (fp16 single) over Q region
    {
        float* sS = (float*)(sma + AOFF_S);
        __half* sA = (__half*)(sma + AOFF_A);
        for (int r = 0; r < 12; r++) {
            int h = wid*12 + r;
            float v0 = sS[h*100 + lane];
            float v1 = sS[h*100 + 32 + lane];
            float v2 = sS[h*100 + 64 + lane];
            float m = fmaxf(v0, fmaxf(v1, v2));
            #pragma unroll
            for (int o = 16; o > 0; o >>= 1) m = fmaxf(m, __shfl_xor_sync(0xffffffffu, m, o));
            float e0 = __expf(v0 - m), e1 = __expf(v1 - m), e2 = __expf(v2 - m);
            float s = e0 + e1 + e2;
            #pragma unroll
            for (int o = 16; o > 0; o >>= 1) s += __shfl_xor_sync(0xffffffffu, s, o);
            float inv = 1.0f / s;
            sA[h*(APITCH/2) + lane]      = __float2half_rn(e0 * inv);
            sA[h*(APITCH/2) + 32 + lane] = __float2half_rn(e1 * inv);
            sA[h*(APITCH/2) + 64 + lane] = __float2half_rn(e2 * inv);
        }
    }
    __syncthreads();

    // ---- AV: O[h,c] = A·(Vh+Vl); c chunks of 64, warp tile 48m x 16n
    const __half* Vh = g_Vhi + (size_t)bw*HH*CC;
    const __half* Vl = g_Vlo + (size_t)bw*HH*CC;
    float* Og = g_Ot + (size_t)bw*HH*CC;
    int cW = warpN * 16;
    int vseg = warpN * 2;

    for (int c0 = 0; c0 < CC; c0 += 64) {
        for (int i = tid; i < 768; i += 256) {
            int g = i >> 3, sg = i & 7;
            uint32_t sw = (uint32_t)(g*128 + ((sg ^ (g & 7))*16));
            size_t go = (size_t)g*CC + c0 + sg*8;
            *(uint4*)(sma + AOFF_VH + sw) = *(const uint4*)(Vh + go);
            *(uint4*)(sma + AOFF_VL + sw) = *(const uint4*)(Vl + go);
        }
        __syncthreads();

        float acc[3][2][4] = {};
        #pragma unroll
        for (int ks = 0; ks < 6; ks++) {
            uint32_t af[3][4], bh[2][2], bl[2][2];
            #pragma unroll
            for (int mi = 0; mi < 3; mi++) {
                int row = m0 + (lane & 15) + mi*16;
                ldsm_x4(af[mi], sb + AOFF_A + (uint32_t)(row*APITCH + ks*32 + (lane >> 4)*16));
            }
            #pragma unroll
            for (int ni = 0; ni < 2; ni++) {
                int row = ks*16 + (lane & 15);
                uint32_t sw16 = (uint32_t)(row*128 + (((vseg + ni) ^ swz)*16));
                ldsm_x2t(bh[ni], sb + AOFF_VH + sw16);
                ldsm_x2t(bl[ni], sb + AOFF_VL + sw16);
            }
            #pragma unroll
            for (int mi = 0; mi < 3; mi++)
                #pragma unroll
                for (int ni = 0; ni < 2; ni++) {
                    mma_h(acc[mi][ni], af[mi], bh[ni]);
                    mma_h(acc[mi][ni], af[mi], bl[ni]);
                }
        }
        __syncthreads();

        float* sO = (float*)(sma + AOFF_O);
        int r = lane >> 2, c2 = (lane & 3) * 2;
        #pragma unroll
        for (int mi = 0; mi < 3; mi++)
            #pragma unroll
            for (int ni = 0; ni < 2; ni++) {
                int row = m0 + mi*16 + r, col = cW + ni*8 + c2;
                *(float2*)&sO[row*68 + col]     = make_float2(acc[mi][ni][0], acc[mi][ni][1]);
                *(float2*)&sO[(row+8)*68 + col] = make_float2(acc[mi][ni][2], acc[mi][ni][3]);
            }
        __syncthreads();

        for (int i = tid; i < 1536; i += 256) {
            int h = i >> 4, c4 = (i & 15) * 4;
            *(float4*)&Og[(size_t)h*CC + c0 + c4] = *(float4*)&sO[h*68 + c4];
        }
        __syncthreads();
    }
}

// ---------------- kernel 3: transpose back + residual ------------------------
__global__ __launch_bounds__(256) void out_kernel(const float* __restrict__ x,
                                                  const float* __restrict__ gamma,
                                                  float* __restrict__ out) {
    __shared__ float tile[32][33];
    int c0 = blockIdx.x * 32;
    int w0 = blockIdx.y * 32;
    int bh = blockIdx.z;
    int b = bh / HH, h = bh % HH;
    int tx = threadIdx.x, ty = threadIdx.y;
    float gm = gamma[0];
    const float* Ob = g_Ot + (size_t)b * WW * HH * CC;
    #pragma unroll
    for (int i = 0; i < 4; i++) {
        int wl = ty + i*8;
        tile[wl][tx] = Ob[(size_t)((w0 + wl)*HH + h)*CC + c0 + tx];
    }
    __syncthreads();
    size_t base = (size_t)b * CC * PP + (size_t)h * WW;
    #pragma unroll
    for (int i = 0; i < 4; i++) {
        int cl = ty + i*8;
        size_t idx = base + (size_t)(c0 + cl) * PP + w0 + tx;
        out[idx] = gm * tile[tx][cl] + x[idx];
    }
}

// ---------------- launcher ---------------------------------------------------
extern "C" void kernel_launch(void* const* d_in, const int* in_sizes, int n_in,
                              void* d_out, int out_size) {
    const float* x     = (const float*)d_in[0];
    const float* Wq    = (const float*)d_in[1];
    const float* bq    = (const float*)d_in[2];
    const float* Wk    = (const float*)d_in[3];
    const float* bk    = (const float*)d_in[4];
    const float* Wv    = (const float*)d_in[5];
    const float* bv    = (const float*)d_in[6];
    const float* gamma = (const float*)d_in[7];
    float* out = (float*)d_out;

    cudaFuncSetAttribute(qkv_mma_kernel, cudaFuncAttributeMaxDynamicSharedMemorySize, QKV_SMEM);
    cudaFuncSetAttribute(attn_mma_kernel, cudaFuncAttributeMaxDynamicSharedMemorySize, ATT_SMEM);

    prep_kernel<<<(JTOT*CC + 255)/256, 256>>>(Wq, bq, Wk, bk, Wv, bv);
    xsplit_kernel<<<(int)((size_t)BB*CC*PP/4/256), 256>>>(x);
    qkv_mma_kernel<<<dim3(PP/64, BB), 256, QKV_SMEM>>>();
    attn_mma_kernel<<<dim3(BB*WW), 256, ATT_SMEM>>>();
    out_kernel<<<dim3(CC/32, WW/32, BB*HH), dim3(32, 8)>>>(x, gamma, out);
}

// round 7
// speedup vs baseline: 2.2663x; 1.0635x over previous
#include <cuda_runtime.h>
#include <cuda_fp16.h>
#include <cstdint>

#define BB 16
#define CC 256
#define HH 96
#define WW 96
#define QKD 64
#define PP (HH*WW)          // 9216
#define JTOT 384

// ---------------- scratch (static device memory; no allocs allowed) ----------
__device__ float g_bcat[JTOT];
__device__ __half g_Whi[JTOT*CC];
__device__ __half g_Wlo[JTOT*CC];
__device__ __half g_Qhi[(size_t)BB*WW*HH*QKD];      // [b*w*h][q]
__device__ __half g_Qlo[(size_t)BB*WW*HH*QKD];
__device__ __half g_Khi[(size_t)BB*WW*HH*QKD];
__device__ __half g_Klo[(size_t)BB*WW*HH*QKD];
__device__ __half g_Vhi[(size_t)BB*WW*HH*CC];       // [b*w*g][c]
__device__ __half g_Vlo[(size_t)BB*WW*HH*CC];
__device__ __half g_Ot[(size_t)BB*WW*HH*CC];        // [b][w][h][c]  fp16

// ---------------- PTX helpers (baseline, sm_103-safe) ------------------------
__device__ __forceinline__ uint32_t smem_u32(const void* p) {
    uint32_t a;
    asm("{ .reg .u64 t; cvta.to.shared.u64 t, %1; cvt.u32.u64 %0, t; }" : "=r"(a) : "l"(p));
    return a;
}
__device__ __forceinline__ void ldsm_x4(uint32_t* r, uint32_t addr) {
    asm volatile("ldmatrix.sync.aligned.m8n8.x4.shared.b16 {%0,%1,%2,%3}, [%4];"
        : "=r"(r[0]), "=r"(r[1]), "=r"(r[2]), "=r"(r[3]) : "r"(addr));
}
__device__ __forceinline__ void ldsm_x2(uint32_t* r, uint32_t addr) {
    asm volatile("ldmatrix.sync.aligned.m8n8.x2.shared.b16 {%0,%1}, [%2];"
        : "=r"(r[0]), "=r"(r[1]) : "r"(addr));
}
__device__ __forceinline__ void ldsm_x2t(uint32_t* r, uint32_t addr) {
    asm volatile("ldmatrix.sync.aligned.m8n8.x2.trans.shared.b16 {%0,%1}, [%2];"
        : "=r"(r[0]), "=r"(r[1]) : "r"(addr));
}
__device__ __forceinline__ void mma_h(float* d, const uint32_t* a, const uint32_t* b) {
    asm volatile("mma.sync.aligned.m16n8k16.row.col.f32.f16.f16.f32 "
        "{%0,%1,%2,%3}, {%4,%5,%6,%7}, {%8,%9}, {%0,%1,%2,%3};"
        : "+f"(d[0]), "+f"(d[1]), "+f"(d[2]), "+f"(d[3])
        : "r"(a[0]), "r"(a[1]), "r"(a[2]), "r"(a[3]), "r"(b[0]), "r"(b[1]));
}
__device__ __forceinline__ void cvt_hilo_h(float4 v, uint2& hi, uint2& lo) {
    __half2 h0 = __float22half2_rn(make_float2(v.x, v.y));
    __half2 h1 = __float22half2_rn(make_float2(v.z, v.w));
    float2 f0 = __half22float2(h0), f1 = __half22float2(h1);
    __half2 l0 = __float22half2_rn(make_float2(v.x - f0.x, v.y - f0.y));
    __half2 l1 = __float22half2_rn(make_float2(v.z - f1.x, v.w - f1.y));
    hi = make_uint2(*(uint32_t*)&h0, *(uint32_t*)&h1);
    lo = make_uint2(*(uint32_t*)&l0, *(uint32_t*)&l1);
}
#define CP_ASYNC16(dst, src) \
    asm volatile("cp.async.cg.shared.global [%0], [%1], 16;" :: "r"(dst), "l"(src))
#define CP_COMMIT() asm volatile("cp.async.commit_group;" ::: "memory")
#define CP_WAIT0()  asm volatile("cp.async.wait_group 0;" ::: "memory")

// ---------------- kernel 0: weight concat + fp16 split -----------------------
__global__ void prep_kernel(const float* __restrict__ Wq, const float* __restrict__ bq,
                            const float* __restrict__ Wk, const float* __restrict__ bk,
                            const float* __restrict__ Wv, const float* __restrict__ bv) {
    int i = blockIdx.x * blockDim.x + threadIdx.x;
    if (i < JTOT*CC) {
        int j = i / CC, k = i % CC;
        float v;
        if (j < 64)       v = Wq[j*CC + k];
        else if (j < 128) v = Wk[(j-64)*CC + k];
        else              v = Wv[(j-128)*CC + k];
        __half h = __float2half_rn(v);
        g_Whi[i] = h;
        g_Wlo[i] = __float2half_rn(v - __half2float(h));
    }
    if (i < JTOT) {
        g_bcat[i] = (i < 64) ? bq[i] : (i < 128) ? bk[i-64] : bv[i-128];
    }
}

// ---------------- kernel 1: QKV projection (fp16 multi-pass warp MMA) --------
// B (x hi/lo) built in-kernel from fp32 x (LDG->cvt->STS). A double-buffered.
// jt 0,1 (Q,K): 3 passes. jt 2..5 (V): 2 passes.
#define OFF_BH   0
#define OFF_BL   32768
#define OFF_A    65536       // 4 x 8KB: buf0 hi/lo, buf1 hi/lo
#define OFF_STG  65536       // epilogue overlay
#define OFF_BIAS 98304
#define QKV_SMEM 99840
#define STGP 66

__global__ __launch_bounds__(256) void qkv_mma_kernel(const float* __restrict__ x) {
    extern __shared__ __align__(128) char smq[];
    uint32_t sb = smem_u32(smq);
    int tid = threadIdx.x, wid = tid >> 5, lane = tid & 31;
    int pBase = blockIdx.x * 64;
    int bz = blockIdx.y;
    int warpM = wid & 1, warpN = wid >> 1;   // 2 x 4
    int jW = warpM * 32, pW = warpN * 16;

    for (int t = tid; t < JTOT; t += 256)
        *(float*)(smq + OFF_BIAS + t*4) = g_bcat[t];

    // A(jt0, ch0) -> buf0 (async; overlaps B conversion below)
    for (int t = tid; t < 512; t += 256) {
        int j = t >> 3, sg = t & 7;
        uint32_t sw = (uint32_t)(j*128 + ((sg ^ (j & 7))*16));
        CP_ASYNC16(sb + OFF_A + sw,        g_Whi + j*CC + sg*8);
        CP_ASYNC16(sb + OFF_A + 8192 + sw, g_Wlo + j*CC + sg*8);
    }
    CP_COMMIT();

    // B resident: load fp32 x, convert to fp16 hi/lo, swizzled 128B rows
    {
        const float* xb = x + (size_t)bz*CC*PP;
        for (int t = tid; t < 4096; t += 256) {
            int k = t >> 4, sg = t & 15;
            float4 v = *(const float4*)&xb[(size_t)k*PP + pBase + sg*4];
            uint2 hi, lo; cvt_hilo_h(v, hi, lo);
            uint32_t sw = (uint32_t)(k*128 + (((sg>>1) ^ (k & 7))*16) + (sg&1)*8);
            *(uint2*)(smq + OFF_BH + sw) = hi;
            *(uint2*)(smq + OFF_BL + sw) = lo;
        }
    }

    int rA   = lane & 15;
    int swzA = rA & 7;
    int aseg = lane >> 4;
    int swzB = lane & 7;
    int bseg = (pW >> 3);

    for (int jt = 0; jt < 6; jt++) {
        float acc[2][2][4] = {};
        bool threepass = (jt < 2);

        for (int ch = 0; ch < 4; ch++) {
            CP_WAIT0();
            __syncthreads();
            if (ch < 3) {
                uint32_t dst = sb + OFF_A + (uint32_t)(((ch+1) & 1) * 16384);
                const __half* sH = g_Whi + (jt*64)*CC + (ch+1)*64;
                const __half* sL = g_Wlo + (jt*64)*CC + (ch+1)*64;
                for (int t = tid; t < 512; t += 256) {
                    int j = t >> 3, sg = t & 7;
                    uint32_t sw = (uint32_t)(j*128 + ((sg ^ (j & 7))*16));
                    CP_ASYNC16(dst + sw,        sH + j*CC + sg*8);
                    CP_ASYNC16(dst + 8192 + sw, sL + j*CC + sg*8);
                }
                CP_COMMIT();
            }
            uint32_t aBufH = sb + OFF_A + (uint32_t)((ch & 1) * 16384);
            uint32_t aBufL = aBufH + 8192;
            #pragma unroll
            for (int pass = 0; pass < 3; pass++) {
                if (pass == 1 && !threepass) continue;
                uint32_t aB = (pass == 2) ? aBufL : aBufH;
                uint32_t bB = sb + ((pass == 1) ? OFF_BL : OFF_BH);
                #pragma unroll
                for (int ksc = 0; ksc < 4; ksc++) {
                    int ks16 = ch*4 + ksc;
                    uint32_t af[2][4], bf[2][2];
                    #pragma unroll
                    for (int mi = 0; mi < 2; mi++) {
                        int row = jW + rA + mi*16;
                        ldsm_x4(af[mi], aB + (uint32_t)(row*128 + (((ksc*2 + aseg) ^ swzA)*16)));
                    }
                    #pragma unroll
                    for (int ni = 0; ni < 2; ni++) {
                        int row = ks16*16 + rA;
                        ldsm_x2t(bf[ni], bB + (uint32_t)(row*128 + (((bseg + ni) ^ swzB)*16)));
                    }
                    #pragma unroll
                    for (int mi = 0; mi < 2; mi++)
                        #pragma unroll
                        for (int ni = 0; ni < 2; ni++)
                            mma_h(acc[mi][ni], af[mi], bf[ni]);
                }
            }
        }
        __syncthreads();

        float* stg = (float*)(smq + OFF_STG);
        {
            int r = lane >> 2, c2 = (lane & 3) * 2;
            #pragma unroll
            for (int mi = 0; mi < 2; mi++)
                #pragma unroll
                for (int ni = 0; ni < 2; ni++) {
                    int j = jW + mi*16 + r;
                    int p = pW + ni*8 + c2;
                    stg[p*STGP + j]         = acc[mi][ni][0];
                    stg[(p+1)*STGP + j]     = acc[mi][ni][1];
                    stg[p*STGP + j + 8]     = acc[mi][ni][2];
                    stg[(p+1)*STGP + j + 8] = acc[mi][ni][3];
                }
        }
        __syncthreads();

        const float* sBias = (const float*)(smq + OFF_BIAS) + jt*64;
        for (int idx = tid; idx < 2048; idx += 256) {
            int pl = idx >> 5, j = (idx & 31) * 2;
            float v0 = stg[pl*STGP + j]     + sBias[j];
            float v1 = stg[pl*STGP + j + 1] + sBias[j + 1];
            __half h0 = __float2half_rn(v0), h1 = __float2half_rn(v1);
            __half l0 = __float2half_rn(v0 - __half2float(h0));
            __half l1 = __float2half_rn(v1 - __half2float(h1));
            __half2 hh = __halves2half2(h0, h1), ll = __halves2half2(l0, l1);
            int p = pBase + pl;
            int h = p / WW, w = p - h*WW;
            size_t col = (size_t)(bz*WW + w)*HH + h;
            if (jt == 0) {
                *(__half2*)(g_Qhi + col*QKD + j) = hh;
                *(__half2*)(g_Qlo + col*QKD + j) = ll;
            } else if (jt == 1) {
                *(__half2*)(g_Khi + col*QKD + j) = hh;
                *(__half2*)(g_Klo + col*QKD + j) = ll;
            } else {
                size_t o = col*CC + (jt-2)*64 + j;
                *(__half2*)(g_Vhi + o) = hh;
                *(__half2*)(g_Vlo + o) = ll;
            }
        }
        __syncthreads();

        if (jt < 5) {
            const __half* sH = g_Whi + ((jt+1)*64)*CC;
            const __half* sL = g_Wlo + ((jt+1)*64)*CC;
            for (int t = tid; t < 512; t += 256) {
                int j = t >> 3, sg = t & 7;
                uint32_t sw = (uint32_t)(j*128 + ((sg ^ (j & 7))*16));
                CP_ASYNC16(sb + OFF_A + sw,        sH + j*CC + sg*8);
                CP_ASYNC16(sb + OFF_A + 8192 + sw, sL + j*CC + sg*8);
            }
            CP_COMMIT();
        }
    }
}

// ---------------- kernel 2: per-(b,w) column attention ------------------------
// Register-resident scores + cross-warp softmax stats; 66KB smem -> 3 CTA/SM.
#define AOFF_QH 0
#define AOFF_QL 12288
#define AOFF_KH 24576
#define AOFF_KL 36864
#define AOFF_STAT 49152        // pmax[4][96] + psum[4][96] = 3072B
#define AOFF_A  0              // fp16 96 x 104 (pitch 208B) overlays Q
#define AOFF_VH 24576          // overlays K
#define AOFF_VL 36864
#define AOFF_O  52224          // fp16 96 x 72 (pitch 144B) = 13824
#define ATT_SMEM 66048
#define APITCH 208

__global__ __launch_bounds__(256, 3) void attn_mma_kernel() {
    extern __shared__ __align__(128) char sma[];
    uint32_t sb = smem_u32(sma);
    int tid = threadIdx.x, wid = tid >> 5, lane = tid & 31;
    int bw = blockIdx.x;
    int swz = lane & 7;

    // ---- stage Q,K (swizzled 128B rows)
    {
        const __half* Qh = g_Qhi + (size_t)bw*HH*QKD;
        const __half* Ql = g_Qlo + (size_t)bw*HH*QKD;
        const __half* Kh = g_Khi + (size_t)bw*HH*QKD;
        const __half* Kl = g_Klo + (size_t)bw*HH*QKD;
        for (int i = tid; i < 768; i += 256) {
            int h = i >> 3, sg = i & 7;
            uint32_t sw = (uint32_t)(h*128 + ((sg ^ (h & 7))*16));
            int go = h*QKD + sg*8;
            *(uint4*)(sma + AOFF_QH + sw) = *(const uint4*)(Qh + go);
            *(uint4*)(sma + AOFF_QL + sw) = *(const uint4*)(Ql + go);
            *(uint4*)(sma + AOFF_KH + sw) = *(const uint4*)(Kh + go);
            *(uint4*)(sma + AOFF_KL + sw) = *(const uint4*)(Kl + go);
        }
    }
    __syncthreads();

    int warpM = wid & 1, warpN = wid >> 1;
    int m0 = warpM * 48;
    int n0 = warpN * 24;
    int rq = lane >> 2, c2 = (lane & 3) * 2;

    // ---- scores: S[h,g] in registers, warp tile 48m x 24n, 3 passes
    float acc[3][3][4] = {};
    #pragma unroll
    for (int pass = 0; pass < 3; pass++) {
        uint32_t aB = sb + ((pass == 2) ? AOFF_QL : AOFF_QH);
        uint32_t bB = sb + ((pass == 1) ? AOFF_KL : AOFF_KH);
        #pragma unroll
        for (int ks = 0; ks < 4; ks++) {
            uint32_t af[3][4], bf[3][2];
            #pragma unroll
            for (int mi = 0; mi < 3; mi++) {
                int row = m0 + (lane & 15) + mi*16;
                ldsm_x4(af[mi], aB + (uint32_t)(row*128 + (((ks*2 + (lane >> 4)) ^ swz)*16)));
            }
            #pragma unroll
            for (int nj = 0; nj < 3; nj++) {
                int row = n0 + nj*8 + (lane & 7);
                ldsm_x2(bf[nj], bB + (uint32_t)(row*128 + (((ks*2 + ((lane >> 3) & 1)) ^ swz)*16)));
            }
            #pragma unroll
            for (int mi = 0; mi < 3; mi++)
                #pragma unroll
                for (int nj = 0; nj < 3; nj++)
                    mma_h(acc[mi][nj], af[mi], bf[nj]);
        }
    }

    // ---- softmax: partial max -> cross-warp -> exp -> partial sum -> normalize
    float* pmax = (float*)(sma + AOFF_STAT);          // [4][96]
    float* psum = (float*)(sma + AOFF_STAT + 1536);   // [4][96]
    #pragma unroll
    for (int mi = 0; mi < 3; mi++) {
        float m0v = fmaxf(fmaxf(acc[mi][0][0], acc[mi][0][1]),
                          fmaxf(acc[mi][1][0], acc[mi][1][1]));
        m0v = fmaxf(m0v, fmaxf(acc[mi][2][0], acc[mi][2][1]));
        float m1v = fmaxf(fmaxf(acc[mi][0][2], acc[mi][0][3]),
                          fmaxf(acc[mi][1][2], acc[mi][1][3]));
        m1v = fmaxf(m1v, fmaxf(acc[mi][2][2], acc[mi][2][3]));
        m0v = fmaxf(m0v, __shfl_xor_sync(0xffffffffu, m0v, 1));
        m0v = fmaxf(m0v, __shfl_xor_sync(0xffffffffu, m0v, 2));
        m1v = fmaxf(m1v, __shfl_xor_sync(0xffffffffu, m1v, 1));
        m1v = fmaxf(m1v, __shfl_xor_sync(0xffffffffu, m1v, 2));
        if ((lane & 3) == 0) {
            pmax[warpN*96 + m0 + mi*16 + rq]     = m0v;
            pmax[warpN*96 + m0 + mi*16 + rq + 8] = m1v;
        }
    }
    __syncthreads();
    #pragma unroll
    for (int mi = 0; mi < 3; mi++) {
        #pragma unroll
        for (int hf = 0; hf < 2; hf++) {
            int row = m0 + mi*16 + rq + hf*8;
            float gm = fmaxf(fmaxf(pmax[row], pmax[96 + row]),
                             fmaxf(pmax[192 + row], pmax[288 + row]));
            float s = 0.f;
            #pragma unroll
            for (int nj = 0; nj < 3; nj++) {
                float e0 = __expf(acc[mi][nj][hf*2]     - gm);
                float e1 = __expf(acc[mi][nj][hf*2 + 1] - gm);
                acc[mi][nj][hf*2] = e0; acc[mi][nj][hf*2 + 1] = e1;
                s += e0 + e1;
            }
            s += __shfl_xor_sync(0xffffffffu, s, 1);
            s += __shfl_xor_sync(0xffffffffu, s, 2);
            if ((lane & 3) == 0) psum[warpN*96 + row] = s;
        }
    }
    __syncthreads();
    {
        __half* sA = (__half*)(sma + AOFF_A);
        #pragma unroll
        for (int mi = 0; mi < 3; mi++) {
            #pragma unroll
            for (int hf = 0; hf < 2; hf++) {
                int row = m0 + mi*16 + rq + hf*8;
                float tot = psum[row] + psum[96 + row] + psum[192 + row] + psum[288 + row];
                float inv = 1.0f / tot;
                #pragma unroll
                for (int nj = 0; nj < 3; nj++) {
                    __half2 a2 = __floats2half2_rn(acc[mi][nj][hf*2] * inv,
                                                   acc[mi][nj][hf*2 + 1] * inv);
                    *(__half2*)&sA[row*(APITCH/2) + n0 + nj*8 + c2] = a2;
                }
            }
        }
    }
    __syncthreads();

    // ---- AV: O[h,c] = A·(Vh+Vl); c chunks of 64, warp tile 48m x 16n
    const __half* Vh = g_Vhi + (size_t)bw*HH*CC;
    const __half* Vl = g_Vlo + (size_t)bw*HH*CC;
    __half* Og = g_Ot + (size_t)bw*HH*CC;
    int cW = warpN * 16;
    int vseg = warpN * 2;

    for (int c0 = 0; c0 < CC; c0 += 64) {
        for (int i = tid; i < 768; i += 256) {
            int g = i >> 3, sg = i & 7;
            uint32_t sw = (uint32_t)(g*128 + ((sg ^ (g & 7))*16));
            size_t go = (size_t)g*CC + c0 + sg*8;
            *(uint4*)(sma + AOFF_VH + sw) = *(const uint4*)(Vh + go);
            *(uint4*)(sma + AOFF_VL + sw) = *(const uint4*)(Vl + go);
        }
        __syncthreads();

        float vacc[3][2][4] = {};
        #pragma unroll
        for (int ks = 0; ks < 6; ks++) {
            uint32_t af[3][4], bh[2][2], bl[2][2];
            #pragma unroll
            for (int mi = 0; mi < 3; mi++) {
                int row = m0 + (lane & 15) + mi*16;
                ldsm_x4(af[mi], sb + AOFF_A + (uint32_t)(row*APITCH + ks*32 + (lane >> 4)*16));
            }
            #pragma unroll
            for (int ni = 0; ni < 2; ni++) {
                int row = ks*16 + (lane & 15);
                uint32_t sw16 = (uint32_t)(row*128 + (((vseg + ni) ^ swz)*16));
                ldsm_x2t(bh[ni], sb + AOFF_VH + sw16);
                ldsm_x2t(bl[ni], sb + AOFF_VL + sw16);
            }
            #pragma unroll
            for (int mi = 0; mi < 3; mi++)
                #pragma unroll
                for (int ni = 0; ni < 2; ni++) {
                    mma_h(vacc[mi][ni], af[mi], bh[ni]);
                    mma_h(vacc[mi][ni], af[mi], bl[ni]);
                }
        }
        __syncthreads();

        __half* sO = (__half*)(sma + AOFF_O);   // pitch 72 halfs
        #pragma unroll
        for (int mi = 0; mi < 3; mi++)
            #pragma unroll
            for (int ni = 0; ni < 2; ni++) {
                int row = m0 + mi*16 + rq, col = cW + ni*8 + c2;
                *(__half2*)&sO[row*72 + col]     = __floats2half2_rn(vacc[mi][ni][0], vacc[mi][ni][1]);
                *(__half2*)&sO[(row+8)*72 + col] = __floats2half2_rn(vacc[mi][ni][2], vacc[mi][ni][3]);
            }
        __syncthreads();

        for (int i = tid; i < 768; i += 256) {
            int h = i >> 3, c8 = (i & 7) * 8;
            *(uint4*)&Og[(size_t)h*CC + c0 + c8] = *(uint4*)&sO[h*72 + c8];
        }
        __syncthreads();
    }
}

// ---------------- kernel 3: transpose back + residual ------------------------
__global__ __launch_bounds__(256) void out_kernel(const float* __restrict__ x,
                                                  const float* __restrict__ gamma,
                                                  float* __restrict__ out) {
    __shared__ float tile[32][33];
    int c0 = blockIdx.x * 32;
    int w0 = blockIdx.y * 32;
    int bh = blockIdx.z;
    int b = bh / HH, h = bh % HH;
    int tx = threadIdx.x, ty = threadIdx.y;
    float gm = gamma[0];
    const __half* Ob = g_Ot + (size_t)b * WW * HH * CC;
    #pragma unroll
    for (int i = 0; i < 4; i++) {
        int wl = ty + i*8;
        tile[wl][tx] = __half2float(Ob[(size_t)((w0 + wl)*HH + h)*CC + c0 + tx]);
    }
    __syncthreads();
    size_t base = (size_t)b * CC * PP + (size_t)h * WW;
    #pragma unroll
    for (int i = 0; i < 4; i++) {
        int cl = ty + i*8;
        size_t idx = base + (size_t)(c0 + cl) * PP + w0 + tx;
        out[idx] = gm * tile[tx][cl] + x[idx];
    }
}

// ---------------- launcher ---------------------------------------------------
extern "C" void kernel_launch(void* const* d_in, const int* in_sizes, int n_in,
                              void* d_out, int out_size) {
    const float* x     = (const float*)d_in[0];
    const float* Wq    = (const float*)d_in[1];
    const float* bq    = (const float*)d_in[2];
    const float* Wk    = (const float*)d_in[3];
    const float* bk    = (const float*)d_in[4];
    const float* Wv    = (const float*)d_in[5];
    const float* bv    = (const float*)d_in[6];
    const float* gamma = (const float*)d_in[7];
    float* out = (float*)d_out;

    cudaFuncSetAttribute(qkv_mma_kernel, cudaFuncAttributeMaxDynamicSharedMemorySize, QKV_SMEM);
    cudaFuncSetAttribute(attn_mma_kernel, cudaFuncAttributeMaxDynamicSharedMemorySize, ATT_SMEM);

    prep_kernel<<<(JTOT*CC + 255)/256, 256>>>(Wq, bq, Wk, bk, Wv, bv);
    qkv_mma_kernel<<<dim3(PP/64, BB), 256, QKV_SMEM>>>(x);
    attn_mma_kernel<<<dim3(BB*WW), 256, ATT_SMEM>>>();
    out_kernel<<<dim3(CC/32, WW/32, BB*HH), dim3(32, 8)>>>(x, gamma, out);
}

// round 8
// speedup vs baseline: 2.5877x; 1.1418x over previous
#include <cuda_runtime.h>
#include <cuda_fp16.h>
#include <cstdint>

#define BB 16
#define CC 256
#define HH 96
#define WW 96
#define QKD 64
#define PP (HH*WW)          // 9216
#define JTOT 384

// ---------------- scratch (static device memory; no allocs allowed) ----------
__device__ float g_bcat[JTOT];
__device__ __half g_Whi[JTOT*CC];
__device__ __half g_Wlo[JTOT*CC];
__device__ __half g_Qhi[(size_t)BB*WW*HH*QKD];      // [b*w*h][q]
__device__ __half g_Qlo[(size_t)BB*WW*HH*QKD];
__device__ __half g_Khi[(size_t)BB*WW*HH*QKD];
__device__ __half g_Klo[(size_t)BB*WW*HH*QKD];
__device__ __half g_Vhi[(size_t)BB*WW*HH*CC];       // [b*w*g][c] single fp16
__device__ __half g_Ot[(size_t)BB*WW*HH*CC];        // [b][w][h][c]  fp16

// ---------------- PTX helpers (baseline, sm_103-safe) ------------------------
__device__ __forceinline__ uint32_t smem_u32(const void* p) {
    uint32_t a;
    asm("{ .reg .u64 t; cvta.to.shared.u64 t, %1; cvt.u32.u64 %0, t; }" : "=r"(a) : "l"(p));
    return a;
}
__device__ __forceinline__ void ldsm_x4(uint32_t* r, uint32_t addr) {
    asm volatile("ldmatrix.sync.aligned.m8n8.x4.shared.b16 {%0,%1,%2,%3}, [%4];"
        : "=r"(r[0]), "=r"(r[1]), "=r"(r[2]), "=r"(r[3]) : "r"(addr));
}
__device__ __forceinline__ void ldsm_x2(uint32_t* r, uint32_t addr) {
    asm volatile("ldmatrix.sync.aligned.m8n8.x2.shared.b16 {%0,%1}, [%2];"
        : "=r"(r[0]), "=r"(r[1]) : "r"(addr));
}
__device__ __forceinline__ void ldsm_x2t(uint32_t* r, uint32_t addr) {
    asm volatile("ldmatrix.sync.aligned.m8n8.x2.trans.shared.b16 {%0,%1}, [%2];"
        : "=r"(r[0]), "=r"(r[1]) : "r"(addr));
}
__device__ __forceinline__ void mma_h(float* d, const uint32_t* a, const uint32_t* b) {
    asm volatile("mma.sync.aligned.m16n8k16.row.col.f32.f16.f16.f32 "
        "{%0,%1,%2,%3}, {%4,%5,%6,%7}, {%8,%9}, {%0,%1,%2,%3};"
        : "+f"(d[0]), "+f"(d[1]), "+f"(d[2]), "+f"(d[3])
        : "r"(a[0]), "r"(a[1]), "r"(a[2]), "r"(a[3]), "r"(b[0]), "r"(b[1]));
}
__device__ __forceinline__ void cvt_hilo_h(float4 v, uint2& hi, uint2& lo) {
    __half2 h0 = __float22half2_rn(make_float2(v.x, v.y));
    __half2 h1 = __float22half2_rn(make_float2(v.z, v.w));
    float2 f0 = __half22float2(h0), f1 = __half22float2(h1);
    __half2 l0 = __float22half2_rn(make_float2(v.x - f0.x, v.y - f0.y));
    __half2 l1 = __float22half2_rn(make_float2(v.z - f1.x, v.w - f1.y));
    hi = make_uint2(*(uint32_t*)&h0, *(uint32_t*)&h1);
    lo = make_uint2(*(uint32_t*)&l0, *(uint32_t*)&l1);
}
#define CP_ASYNC16(dst, src) \
    asm volatile("cp.async.cg.shared.global [%0], [%1], 16;" :: "r"(dst), "l"(src))
#define CP_COMMIT() asm volatile("cp.async.commit_group;" ::: "memory")
#define CP_WAIT0()  asm volatile("cp.async.wait_group 0;" ::: "memory")

// ---------------- kernel 0: weight concat + fp16 split -----------------------
__global__ void prep_kernel(const float* __restrict__ Wq, const float* __restrict__ bq,
                            const float* __restrict__ Wk, const float* __restrict__ bk,
                            const float* __restrict__ Wv, const float* __restrict__ bv) {
    int i = blockIdx.x * blockDim.x + threadIdx.x;
    if (i < JTOT*CC) {
        int j = i / CC, k = i % CC;
        float v;
        if (j < 64)       v = Wq[j*CC + k];
        else if (j < 128) v = Wk[(j-64)*CC + k];
        else              v = Wv[(j-128)*CC + k];
        __half h = __float2half_rn(v);
        g_Whi[i] = h;
        g_Wlo[i] = __float2half_rn(v - __half2float(h));
    }
    if (i < JTOT) {
        g_bcat[i] = (i < 64) ? bq[i] : (i < 128) ? bk[i-64] : bv[i-128];
    }
}

// ---------------- kernel 1: QKV projection (fp16 warp MMA) -------------------
// jt 0,1 (Q,K): 3 passes (hi/lo both sides). jt 2..5 (V): 1 pass (hi only).
#define OFF_BH   0
#define OFF_BL   32768
#define OFF_A    65536       // 4 x 8KB: buf0 hi/lo, buf1 hi/lo
#define OFF_STG  65536       // epilogue overlay
#define OFF_BIAS 98304
#define QKV_SMEM 99840
#define STGP 66

__global__ __launch_bounds__(256) void qkv_mma_kernel(const float* __restrict__ x) {
    extern __shared__ __align__(128) char smq[];
    uint32_t sb = smem_u32(smq);
    int tid = threadIdx.x, wid = tid >> 5, lane = tid & 31;
    int pBase = blockIdx.x * 64;
    int bz = blockIdx.y;
    int warpM = wid & 1, warpN = wid >> 1;   // 2 x 4
    int jW = warpM * 32, pW = warpN * 16;

    for (int t = tid; t < JTOT; t += 256)
        *(float*)(smq + OFF_BIAS + t*4) = g_bcat[t];

    // A(jt0, ch0) -> buf0
    for (int t = tid; t < 512; t += 256) {
        int j = t >> 3, sg = t & 7;
        uint32_t sw = (uint32_t)(j*128 + ((sg ^ (j & 7))*16));
        CP_ASYNC16(sb + OFF_A + sw,        g_Whi + j*CC + sg*8);
        CP_ASYNC16(sb + OFF_A + 8192 + sw, g_Wlo + j*CC + sg*8);
    }
    CP_COMMIT();

    // B resident: fp32 x -> fp16 hi/lo, swizzled 128B rows
    {
        const float* xb = x + (size_t)bz*CC*PP;
        for (int t = tid; t < 4096; t += 256) {
            int k = t >> 4, sg = t & 15;
            float4 v = *(const float4*)&xb[(size_t)k*PP + pBase + sg*4];
            uint2 hi, lo; cvt_hilo_h(v, hi, lo);
            uint32_t sw = (uint32_t)(k*128 + (((sg>>1) ^ (k & 7))*16) + (sg&1)*8);
            *(uint2*)(smq + OFF_BH + sw) = hi;
            *(uint2*)(smq + OFF_BL + sw) = lo;
        }
    }

    int rA   = lane & 15;
    int swzA = rA & 7;
    int aseg = lane >> 4;
    int swzB = lane & 7;
    int bseg = (pW >> 3);

    for (int jt = 0; jt < 6; jt++) {
        float acc[2][2][4] = {};
        bool threepass = (jt < 2);

        for (int ch = 0; ch < 4; ch++) {
            CP_WAIT0();
            __syncthreads();
            if (ch < 3) {
                uint32_t dst = sb + OFF_A + (uint32_t)(((ch+1) & 1) * 16384);
                const __half* sH = g_Whi + (jt*64)*CC + (ch+1)*64;
                const __half* sL = g_Wlo + (jt*64)*CC + (ch+1)*64;
                for (int t = tid; t < 512; t += 256) {
                    int j = t >> 3, sg = t & 7;
                    uint32_t sw = (uint32_t)(j*128 + ((sg ^ (j & 7))*16));
                    CP_ASYNC16(dst + sw,        sH + j*CC + sg*8);
                    CP_ASYNC16(dst + 8192 + sw, sL + j*CC + sg*8);
                }
                CP_COMMIT();
            }
            uint32_t aBufH = sb + OFF_A + (uint32_t)((ch & 1) * 16384);
            uint32_t aBufL = aBufH + 8192;
            #pragma unroll
            for (int pass = 0; pass < 3; pass++) {
                if (!threepass && pass != 0) continue;
                uint32_t aB = (pass == 2) ? aBufL : aBufH;
                uint32_t bB = sb + ((pass == 1) ? OFF_BL : OFF_BH);
                #pragma unroll
                for (int ksc = 0; ksc < 4; ksc++) {
                    int ks16 = ch*4 + ksc;
                    uint32_t af[2][4], bf[2][2];
                    #pragma unroll
                    for (int mi = 0; mi < 2; mi++) {
                        int row = jW + rA + mi*16;
                        ldsm_x4(af[mi], aB + (uint32_t)(row*128 + (((ksc*2 + aseg) ^ swzA)*16)));
                    }
                    #pragma unroll
                    for (int ni = 0; ni < 2; ni++) {
                        int row = ks16*16 + rA;
                        ldsm_x2t(bf[ni], bB + (uint32_t)(row*128 + (((bseg + ni) ^ swzB)*16)));
                    }
                    #pragma unroll
                    for (int mi = 0; mi < 2; mi++)
                        #pragma unroll
                        for (int ni = 0; ni < 2; ni++)
                            mma_h(acc[mi][ni], af[mi], bf[ni]);
                }
            }
        }
        __syncthreads();

        float* stg = (float*)(smq + OFF_STG);
        {
            int r = lane >> 2, c2 = (lane & 3) * 2;
            #pragma unroll
            for (int mi = 0; mi < 2; mi++)
                #pragma unroll
                for (int ni = 0; ni < 2; ni++) {
                    int j = jW + mi*16 + r;
                    int p = pW + ni*8 + c2;
                    stg[p*STGP + j]         = acc[mi][ni][0];
                    stg[(p+1)*STGP + j]     = acc[mi][ni][1];
                    stg[p*STGP + j + 8]     = acc[mi][ni][2];
                    stg[(p+1)*STGP + j + 8] = acc[mi][ni][3];
                }
        }
        __syncthreads();

        const float* sBias = (const float*)(smq + OFF_BIAS) + jt*64;
        for (int idx = tid; idx < 2048; idx += 256) {
            int pl = idx >> 5, j = (idx & 31) * 2;
            float v0 = stg[pl*STGP + j]     + sBias[j];
            float v1 = stg[pl*STGP + j + 1] + sBias[j + 1];
            __half h0 = __float2half_rn(v0), h1 = __float2half_rn(v1);
            __half2 hh = __halves2half2(h0, h1);
            int p = pBase + pl;
            int h = p / WW, w = p - h*WW;
            size_t col = (size_t)(bz*WW + w)*HH + h;
            if (jt == 0) {
                __half2 ll = __halves2half2(__float2half_rn(v0 - __half2float(h0)),
                                            __float2half_rn(v1 - __half2float(h1)));
                *(__half2*)(g_Qhi + col*QKD + j) = hh;
                *(__half2*)(g_Qlo + col*QKD + j) = ll;
            } else if (jt == 1) {
                __half2 ll = __halves2half2(__float2half_rn(v0 - __half2float(h0)),
                                            __float2half_rn(v1 - __half2float(h1)));
                *(__half2*)(g_Khi + col*QKD + j) = hh;
                *(__half2*)(g_Klo + col*QKD + j) = ll;
            } else {
                *(__half2*)(g_Vhi + col*CC + (jt-2)*64 + j) = hh;
            }
        }
        __syncthreads();

        if (jt < 5) {
            const __half* sH = g_Whi + ((jt+1)*64)*CC;
            const __half* sL = g_Wlo + ((jt+1)*64)*CC;
            for (int t = tid; t < 512; t += 256) {
                int j = t >> 3, sg = t & 7;
                uint32_t sw = (uint32_t)(j*128 + ((sg ^ (j & 7))*16));
                CP_ASYNC16(sb + OFF_A + sw,        sH + j*CC + sg*8);
                CP_ASYNC16(sb + OFF_A + 8192 + sw, sL + j*CC + sg*8);
            }
            CP_COMMIT();
        }
    }
}

// ---------------- kernel 2: per-(b,w) column attention ------------------------
// Register-resident scores, cross-warp softmax, single-fp16 V. 52.2KB smem.
#define AOFF_QH 0
#define AOFF_QL 12288
#define AOFF_KH 24576
#define AOFF_KL 36864
#define AOFF_STAT 49152        // pmax[4][96] + psum[4][96] = 3072B
#define AOFF_A  0              // fp16 96 x 104 (pitch 208B) overlays Q
#define AOFF_VH 24576          // overlays KH
#define AOFF_O  36864          // fp16 96 x 72 = 13824 (overlays KL+STAT region tail)
#define ATT_SMEM 52224
#define APITCH 208

__global__ __launch_bounds__(256) void attn_mma_kernel() {
    extern __shared__ __align__(128) char sma[];
    uint32_t sb = smem_u32(sma);
    int tid = threadIdx.x, wid = tid >> 5, lane = tid & 31;
    int bw = blockIdx.x;
    int swz = lane & 7;

    // ---- stage Q,K (swizzled 128B rows)
    {
        const __half* Qh = g_Qhi + (size_t)bw*HH*QKD;
        const __half* Ql = g_Qlo + (size_t)bw*HH*QKD;
        const __half* Kh = g_Khi + (size_t)bw*HH*QKD;
        const __half* Kl = g_Klo + (size_t)bw*HH*QKD;
        for (int i = tid; i < 768; i += 256) {
            int h = i >> 3, sg = i & 7;
            uint32_t sw = (uint32_t)(h*128 + ((sg ^ (h & 7))*16));
            int go = h*QKD + sg*8;
            *(uint4*)(sma + AOFF_QH + sw) = *(const uint4*)(Qh + go);
            *(uint4*)(sma + AOFF_QL + sw) = *(const uint4*)(Ql + go);
            *(uint4*)(sma + AOFF_KH + sw) = *(const uint4*)(Kh + go);
            *(uint4*)(sma + AOFF_KL + sw) = *(const uint4*)(Kl + go);
        }
    }
    __syncthreads();

    int warpM = wid & 1, warpN = wid >> 1;
    int m0 = warpM * 48;
    int n0 = warpN * 24;
    int rq = lane >> 2, c2 = (lane & 3) * 2;

    // ---- scores: register-resident, warp tile 48m x 24n, 3 passes
    float acc[3][3][4] = {};
    #pragma unroll
    for (int pass = 0; pass < 3; pass++) {
        uint32_t aB = sb + ((pass == 2) ? AOFF_QL : AOFF_QH);
        uint32_t bB = sb + ((pass == 1) ? AOFF_KL : AOFF_KH);
        #pragma unroll
        for (int ks = 0; ks < 4; ks++) {
            uint32_t af[3][4], bf[3][2];
            #pragma unroll
            for (int mi = 0; mi < 3; mi++) {
                int row = m0 + (lane & 15) + mi*16;
                ldsm_x4(af[mi], aB + (uint32_t)(row*128 + (((ks*2 + (lane >> 4)) ^ swz)*16)));
            }
            #pragma unroll
            for (int nj = 0; nj < 3; nj++) {
                int row = n0 + nj*8 + (lane & 7);
                ldsm_x2(bf[nj], bB + (uint32_t)(row*128 + (((ks*2 + ((lane >> 3) & 1)) ^ swz)*16)));
            }
            #pragma unroll
            for (int mi = 0; mi < 3; mi++)
                #pragma unroll
                for (int nj = 0; nj < 3; nj++)
                    mma_h(acc[mi][nj], af[mi], bf[nj]);
        }
    }

    // ---- softmax: partial max -> cross-warp -> exp -> partial sum -> normalize
    float* pmax = (float*)(sma + AOFF_STAT);          // [4][96]
    float* psum = (float*)(sma + AOFF_STAT + 1536);   // [4][96]
    #pragma unroll
    for (int mi = 0; mi < 3; mi++) {
        float m0v = fmaxf(fmaxf(acc[mi][0][0], acc[mi][0][1]),
                          fmaxf(acc[mi][1][0], acc[mi][1][1]));
        m0v = fmaxf(m0v, fmaxf(acc[mi][2][0], acc[mi][2][1]));
        float m1v = fmaxf(fmaxf(acc[mi][0][2], acc[mi][0][3]),
                          fmaxf(acc[mi][1][2], acc[mi][1][3]));
        m1v = fmaxf(m1v, fmaxf(acc[mi][2][2], acc[mi][2][3]));
        m0v = fmaxf(m0v, __shfl_xor_sync(0xffffffffu, m0v, 1));
        m0v = fmaxf(m0v, __shfl_xor_sync(0xffffffffu, m0v, 2));
        m1v = fmaxf(m1v, __shfl_xor_sync(0xffffffffu, m1v, 1));
        m1v = fmaxf(m1v, __shfl_xor_sync(0xffffffffu, m1v, 2));
        if ((lane & 3) == 0) {
            pmax[warpN*96 + m0 + mi*16 + rq]     = m0v;
            pmax[warpN*96 + m0 + mi*16 + rq + 8] = m1v;
        }
    }
    __syncthreads();
    #pragma unroll
    for (int mi = 0; mi < 3; mi++) {
        #pragma unroll
        for (int hf = 0; hf < 2; hf++) {
            int row = m0 + mi*16 + rq + hf*8;
            float gm = fmaxf(fmaxf(pmax[row], pmax[96 + row]),
                             fmaxf(pmax[192 + row], pmax[288 + row]));
            float s = 0.f;
            #pragma unroll
            for (int nj = 0; nj < 3; nj++) {
                float e0 = __expf(acc[mi][nj][hf*2]     - gm);
                float e1 = __expf(acc[mi][nj][hf*2 + 1] - gm);
                acc[mi][nj][hf*2] = e0; acc[mi][nj][hf*2 + 1] = e1;
                s += e0 + e1;
            }
            s += __shfl_xor_sync(0xffffffffu, s, 1);
            s += __shfl_xor_sync(0xffffffffu, s, 2);
            if ((lane & 3) == 0) psum[warpN*96 + row] = s;
        }
    }
    __syncthreads();
    {
        __half* sA = (__half*)(sma + AOFF_A);
        #pragma unroll
        for (int mi = 0; mi < 3; mi++) {
            #pragma unroll
            for (int hf = 0; hf < 2; hf++) {
                int row = m0 + mi*16 + rq + hf*8;
                float tot = psum[row] + psum[96 + row] + psum[192 + row] + psum[288 + row];
                float inv = 1.0f / tot;
                #pragma unroll
                for (int nj = 0; nj < 3; nj++) {
                    __half2 a2 = __floats2half2_rn(acc[mi][nj][hf*2] * inv,
                                                   acc[mi][nj][hf*2 + 1] * inv);
                    *(__half2*)&sA[row*(APITCH/2) + n0 + nj*8 + c2] = a2;
                }
            }
        }
    }
    __syncthreads();

    // ---- AV: O[h,c] = A·Vh; c chunks of 64, warp tile 48m x 16n
    const __half* Vh = g_Vhi + (size_t)bw*HH*CC;
    __half* Og = g_Ot + (size_t)bw*HH*CC;
    int cW = warpN * 16;
    int vseg = warpN * 2;

    for (int c0 = 0; c0 < CC; c0 += 64) {
        for (int i = tid; i < 768; i += 256) {
            int g = i >> 3, sg = i & 7;
            uint32_t sw = (uint32_t)(g*128 + ((sg ^ (g & 7))*16));
            *(uint4*)(sma + AOFF_VH + sw) = *(const uint4*)(Vh + (size_t)g*CC + c0 + sg*8);
        }
        __syncthreads();

        float vacc[3][2][4] = {};
        #pragma unroll
        for (int ks = 0; ks < 6; ks++) {
            uint32_t af[3][4], bh[2][2];
            #pragma unroll
            for (int mi = 0; mi < 3; mi++) {
                int row = m0 + (lane & 15) + mi*16;
                ldsm_x4(af[mi], sb + AOFF_A + (uint32_t)(row*APITCH + ks*32 + (lane >> 4)*16));
            }
            #pragma unroll
            for (int ni = 0; ni < 2; ni++) {
                int row = ks*16 + (lane & 15);
                ldsm_x2t(bh[ni], sb + AOFF_VH + (uint32_t)(row*128 + (((vseg + ni) ^ swz)*16)));
            }
            #pragma unroll
            for (int mi = 0; mi < 3; mi++)
                #pragma unroll
                for (int ni = 0; ni < 2; ni++)
                    mma_h(vacc[mi][ni], af[mi], bh[ni]);
        }
        __syncthreads();

        __half* sO = (__half*)(sma + AOFF_O);   // pitch 72 halfs
        #pragma unroll
        for (int mi = 0; mi < 3; mi++)
            #pragma unroll
            for (int ni = 0; ni < 2; ni++) {
                int row = m0 + mi*16 + rq, col = cW + ni*8 + c2;
                *(__half2*)&sO[row*72 + col]     = __floats2half2_rn(vacc[mi][ni][0], vacc[mi][ni][1]);
                *(__half2*)&sO[(row+8)*72 + col] = __floats2half2_rn(vacc[mi][ni][2], vacc[mi][ni][3]);
            }
        __syncthreads();

        for (int i = tid; i < 768; i += 256) {
            int h = i >> 3, c8 = (i & 7) * 8;
            *(uint4*)&Og[(size_t)h*CC + c0 + c8] = *(uint4*)&sO[h*72 + c8];
        }
        __syncthreads();
    }
}

// ---------------- kernel 3: transpose back + residual ------------------------
__global__ __launch_bounds__(256) void out_kernel(const float* __restrict__ x,
                                                  const float* __restrict__ gamma,
                                                  float* __restrict__ out) {
    __shared__ float tile[32][33];
    int c0 = blockIdx.x * 32;
    int w0 = blockIdx.y * 32;
    int bh = blockIdx.z;
    int b = bh / HH, h = bh % HH;
    int tx = threadIdx.x, ty = threadIdx.y;
    float gm = gamma[0];
    const __half* Ob = g_Ot + (size_t)b * WW * HH * CC;
    #pragma unroll
    for (int i = 0; i < 4; i++) {
        int wl = ty + i*8;
        tile[wl][tx] = __half2float(Ob[(size_t)((w0 + wl)*HH + h)*CC + c0 + tx]);
    }
    __syncthreads();
    size_t base = (size_t)b * CC * PP + (size_t)h * WW;
    #pragma unroll
    for (int i = 0; i < 4; i++) {
        int cl = ty + i*8;
        size_t idx = base + (size_t)(c0 + cl) * PP + w0 + tx;
        out[idx] = gm * tile[tx][cl] + x[idx];
    }
}

// ---------------- launcher ---------------------------------------------------
extern "C" void kernel_launch(void* const* d_in, const int* in_sizes, int n_in,
                              void* d_out, int out_size) {
    const float* x     = (const float*)d_in[0];
    const float* Wq    = (const float*)d_in[1];
    const float* bq    = (const float*)d_in[2];
    const float* Wk    = (const float*)d_in[3];
    const float* bk    = (const float*)d_in[4];
    const float* Wv    = (const float*)d_in[5];
    const float* bv    = (const float*)d_in[6];
    const float* gamma = (const float*)d_in[7];
    float* out = (float*)d_out;

    cudaFuncSetAttribute(qkv_mma_kernel, cudaFuncAttributeMaxDynamicSharedMemorySize, QKV_SMEM);
    cudaFuncSetAttribute(attn_mma_kernel, cudaFuncAttributeMaxDynamicSharedMemorySize, ATT_SMEM);

    prep_kernel<<<(JTOT*CC + 255)/256, 256>>>(Wq, bq, Wk, bk, Wv, bv);
    qkv_mma_kernel<<<dim3(PP/64, BB), 256, QKV_SMEM>>>(x);
    attn_mma_kernel<<<dim3(BB*WW), 256, ATT_SMEM>>>();
    out_kernel<<<dim3(CC/32, WW/32, BB*HH), dim3(32, 8)>>>(x, gamma, out);
}